// round 3
// baseline (speedup 1.0000x reference)
#include <cuda_runtime.h>
#include <cuda_bf16.h>
#include <math.h>

// ---------------- problem constants ----------------
#define BB   2
#define TT   1024
#define DD   1024
#define NTOK (BB*TT)          // 2048
#define HQ   16
#define HKV  4
#define GQ   4                // HQ/HKV
#define KD   64
#define VD   64
#define EE   8
#define TOPK 2
#define CAP  1024             // floor(2048*0.5)
#define HID  2048
#define EPS  1e-6f

// ---------------- scratch (static device memory; no allocation) ----------------
__device__ float g_h   [NTOK*DD];        // rmsnorm1 out
__device__ float g_q   [NTOK*HQ*KD];
__device__ float g_k   [NTOK*HKV*KD];
__device__ float g_v   [NTOK*HKV*VD];
__device__ float g_attn[NTOK*HQ*VD];
__device__ float g_x1  [NTOK*DD];        // x + attn@wo
__device__ float g_h2  [NTOK*DD];        // rmsnorm2 out
__device__ float g_gate[NTOK*TOPK];
__device__ int   g_expert[NTOK*TOPK];
__device__ int   g_slot  [NTOK*TOPK];
__device__ int   g_keep  [NTOK*TOPK];
__device__ float g_grouped[EE*CAP*DD];   // dispatched tokens
__device__ float g_t1[EE*CAP*HID];       // x@w1, later gelu(prod)
__device__ float g_t2[EE*CAP*HID];       // x@w2
__device__ float g_eout[EE*CAP*DD];

// ---------------- rmsnorm ----------------
__global__ void rmsnorm_kernel(const float* __restrict__ x, const float* __restrict__ scale,
                               float* __restrict__ out) {
    int n = blockIdx.x;
    int tid = threadIdx.x;
    __shared__ float red[256];
    const float* xr = x + (long long)n * DD;
    float ss = 0.f;
    for (int d = tid; d < DD; d += 256) { float v = xr[d]; ss += v * v; }
    red[tid] = ss; __syncthreads();
    for (int s = 128; s > 0; s >>= 1) { if (tid < s) red[tid] += red[tid + s]; __syncthreads(); }
    float inv = rsqrtf(red[0] / (float)DD + EPS);
    float* o = out + (long long)n * DD;
    for (int d = tid; d < DD; d += 256) o[d] = xr[d] * inv * scale[d];
}

// ---------------- classic 128x128x8 fp32 SGEMM (optionally batched, optional residual) ----------------
__global__ __launch_bounds__(256)
void sgemm128(const float* __restrict__ A, const float* __restrict__ B,
              float* __restrict__ C, const float* __restrict__ Res,
              int M, int N, int K,
              long long sA, long long sB, long long sC) {
    A += (long long)blockIdx.z * sA;
    B += (long long)blockIdx.z * sB;
    C += (long long)blockIdx.z * sC;
    __shared__ float As[8][128];
    __shared__ float Bs[8][128];
    int tid = threadIdx.x;
    int tx = tid & 15, ty = tid >> 4;
    int rowBase = blockIdx.y * 128;
    int colBase = blockIdx.x * 128;
    int aRow = tid >> 1;            // 0..127
    int aCol = (tid & 1) * 4;       // 0 or 4
    int bRow = tid >> 5;            // 0..7
    int bCol = (tid & 31) * 4;      // 0..124
    float acc[8][8];
#pragma unroll
    for (int i = 0; i < 8; i++)
#pragma unroll
        for (int j = 0; j < 8; j++) acc[i][j] = 0.f;

    for (int k0 = 0; k0 < K; k0 += 8) {
        float4 a4 = *reinterpret_cast<const float4*>(&A[(long long)(rowBase + aRow) * K + k0 + aCol]);
        As[aCol + 0][aRow] = a4.x; As[aCol + 1][aRow] = a4.y;
        As[aCol + 2][aRow] = a4.z; As[aCol + 3][aRow] = a4.w;
        float4 b4 = *reinterpret_cast<const float4*>(&B[(long long)(k0 + bRow) * N + colBase + bCol]);
        *reinterpret_cast<float4*>(&Bs[bRow][bCol]) = b4;
        __syncthreads();
#pragma unroll
        for (int kk = 0; kk < 8; kk++) {
            float ra[8], rb[8];
            *reinterpret_cast<float4*>(&ra[0]) = *reinterpret_cast<const float4*>(&As[kk][ty * 8]);
            *reinterpret_cast<float4*>(&ra[4]) = *reinterpret_cast<const float4*>(&As[kk][ty * 8 + 4]);
            *reinterpret_cast<float4*>(&rb[0]) = *reinterpret_cast<const float4*>(&Bs[kk][tx * 8]);
            *reinterpret_cast<float4*>(&rb[4]) = *reinterpret_cast<const float4*>(&Bs[kk][tx * 8 + 4]);
#pragma unroll
            for (int i = 0; i < 8; i++)
#pragma unroll
                for (int j = 0; j < 8; j++) acc[i][j] += ra[i] * rb[j];
        }
        __syncthreads();
    }
#pragma unroll
    for (int i = 0; i < 8; i++) {
        long long r = rowBase + ty * 8 + i;
#pragma unroll
        for (int j = 0; j < 8; j += 4) {
            long long c = colBase + tx * 8 + j;
            float4 o;
            o.x = acc[i][j]; o.y = acc[i][j + 1]; o.z = acc[i][j + 2]; o.w = acc[i][j + 3];
            if (Res) {
                float4 r4 = *reinterpret_cast<const float4*>(&Res[r * N + c]);
                o.x += r4.x; o.y += r4.y; o.z += r4.z; o.w += r4.w;
            }
            *reinterpret_cast<float4*>(&C[r * N + c]) = o;
        }
    }
}

// ---------------- rope (in-place, per (token,head) of 64 dims) ----------------
__global__ void rope_kernel(float* __restrict__ data, int H, long long total) {
    long long i = (long long)blockIdx.x * blockDim.x + threadIdx.x;
    if (i >= total) return;
    int half = (int)(i & 31);               // 0..31
    long long nh = i >> 5;                  // token*H + h
    long long tok = nh / H;
    int t = (int)(tok % TT);
    float theta = __powf(10000.0f, -(float)(2 * half) / 64.0f);
    float ang = (float)t * theta;
    float c, s;
    __sincosf(ang, &s, &c);
    // higher precision: use sincosf (precise) — replaced below
    s = sinf(ang); c = cosf(ang);
    float* p = data + nh * 64;
    float x1 = p[half], x2 = p[half + 32];
    p[half]      = x1 * c - x2 * s;
    p[half + 32] = x2 * c + x1 * s;
}

// ---------------- attention: one block per (t, hq, b) ----------------
__global__ __launch_bounds__(128)
void attn_kernel(const float* __restrict__ q, const float* __restrict__ k,
                 const float* __restrict__ v, float* __restrict__ out) {
    int t = blockIdx.x, hq = blockIdx.y, b = blockIdx.z;
    int kv = hq >> 2; // hq / G
    __shared__ float qs[64];
    __shared__ float sc[TT];
    __shared__ float red[128];
    int tid = threadIdx.x;
    const float* qp = q + ((long long)(b * TT + t) * HQ + hq) * 64;
    if (tid < 64) qs[tid] = qp[tid];
    __syncthreads();
    int L = t + 1;
    float lmax = -1e30f;
    for (int s = tid; s < L; s += 128) {
        const float* kp = k + ((long long)(b * TT + s) * HKV + kv) * 64;
        float dot = 0.f;
#pragma unroll
        for (int j = 0; j < 64; j++) dot += qs[j] * kp[j];
        dot *= 0.125f;
        sc[s] = dot;
        lmax = fmaxf(lmax, dot);
    }
    red[tid] = lmax; __syncthreads();
    for (int s = 64; s > 0; s >>= 1) { if (tid < s) red[tid] = fmaxf(red[tid], red[tid + s]); __syncthreads(); }
    float m = red[0]; __syncthreads();
    float lsum = 0.f;
    for (int s = tid; s < L; s += 128) { float e = expf(sc[s] - m); sc[s] = e; lsum += e; }
    red[tid] = lsum; __syncthreads();
    for (int s = 64; s > 0; s >>= 1) { if (tid < s) red[tid] += red[tid + s]; __syncthreads(); }
    float inv = 1.0f / red[0];
    // accumulate over keys; 64 threads each own one v-dim
    if (tid < 64) {
        float acc = 0.f;
        const float* vb = v + ((long long)(b * TT) * HKV + kv) * 64 + tid;
        for (int s = 0; s < L; s++) acc += sc[s] * vb[(long long)s * HKV * 64];
        out[((long long)(b * TT + t) * HQ + hq) * 64 + tid] = acc * inv;
    }
}

// ---------------- router: logits, top-2, softmax gate ----------------
__global__ void router_kernel(const float* __restrict__ h2, const float* __restrict__ rw,
                              const float* __restrict__ rb,
                              float* __restrict__ gate, int* __restrict__ expert) {
    int n = blockIdx.x;
    int tid = threadIdx.x;
    __shared__ float part[128][8];
    float acc[8];
#pragma unroll
    for (int e = 0; e < 8; e++) acc[e] = 0.f;
    const float* xr = h2 + (long long)n * DD;
    for (int d = tid; d < DD; d += 128) {
        float xv = xr[d];
#pragma unroll
        for (int e = 0; e < 8; e++) acc[e] += xv * rw[d * 8 + e];
    }
#pragma unroll
    for (int e = 0; e < 8; e++) part[tid][e] = acc[e];
    __syncthreads();
    if (tid < 8) {
        float s = rb[tid];
        for (int i = 0; i < 128; i++) s += part[i][tid];
        part[0][tid] = s;
    }
    __syncthreads();
    if (tid == 0) {
        float lg[8];
#pragma unroll
        for (int e = 0; e < 8; e++) lg[e] = part[0][e];
        int i0 = 0;
        for (int e = 1; e < 8; e++) if (lg[e] > lg[i0]) i0 = e;
        int i1 = -1;
        for (int e = 0; e < 8; e++) {
            if (e == i0) continue;
            if (i1 < 0 || lg[e] > lg[i1]) i1 = e;
        }
        float a = lg[i0], bq = lg[i1];
        float ea = expf(a - a), eb = expf(bq - a);
        float s = ea + eb;
        gate[n * 2] = ea / s; gate[n * 2 + 1] = eb / s;
        expert[n * 2] = i0;   expert[n * 2 + 1] = i1;
    }
}

// ---------------- capacity masking (exact reference semantics), warp-per-expert ----------------
__global__ void capacity_kernel(const int* __restrict__ expert,
                                int* __restrict__ slot, int* __restrict__ keep) {
    int w = threadIdx.x >> 5;   // expert id (8 warps)
    int lane = threadIdx.x & 31;
    if (w >= EE) return;
    int c0 = 0, c1 = 0;
    unsigned le = 0xffffffffu >> (31 - lane); // lanemask_le
    for (int base = 0; base < NTOK; base += 32) {
        int n = base + lane;
        int e0 = expert[n * 2], e1 = expert[n * 2 + 1];
        unsigned m0 = __ballot_sync(0xffffffffu, e0 == w);
        unsigned m1 = __ballot_sync(0xffffffffu, e1 == w);
        int inc0 = __popc(m0 & le);
        int inc1 = __popc(m1 & le);
        if (e0 == w) {
            int p0 = c0 + inc0;               // inclusive cumsum over tokens, slot0 only
            keep[n * 2] = (p0 < CAP) ? 1 : 0;
            slot[n * 2] = p0;
        }
        if (e1 == w) {
            int p1 = c0 + inc0 + c1 + inc1;   // cumsum over tokens then over k
            keep[n * 2 + 1] = (p1 < CAP) ? 1 : 0;
            slot[n * 2 + 1] = p1;
        }
        c0 += __popc(m0); c1 += __popc(m1);
    }
}

// ---------------- zero scratch ----------------
__global__ void zero_kernel(float* __restrict__ p, long long n) {
    long long i = (long long)blockIdx.x * blockDim.x + threadIdx.x;
    long long stride = (long long)gridDim.x * blockDim.x;
    for (; i < n; i += stride) p[i] = 0.f;
}

// ---------------- dispatch (accumulate: colliding slots SUM, per reference) ----------------
__global__ void dispatch_kernel(const float* __restrict__ h2, const int* __restrict__ expert,
                                const int* __restrict__ slot, const int* __restrict__ keep,
                                float* __restrict__ grouped) {
    int idx = blockIdx.x;  // (token, k)
    if (!keep[idx]) return;
    int n = idx >> 1;
    int e = expert[idx], p = slot[idx];
    float* dst = grouped + ((long long)e * CAP + p) * DD;
    const float* src = h2 + (long long)n * DD;
    for (int d = threadIdx.x; d < DD; d += blockDim.x) atomicAdd(&dst[d], src[d]);
}

// ---------------- gelu(t1*t2) -> t1 (tanh approximation, jax default) ----------------
__global__ void gelu_mul_kernel(float* __restrict__ t1, const float* __restrict__ t2, long long n) {
    long long i = (long long)blockIdx.x * blockDim.x + threadIdx.x;
    long long stride = (long long)gridDim.x * blockDim.x;
    for (; i < n; i += stride) {
        float x = t1[i] * t2[i];
        float inner = 0.7978845608028654f * (x + 0.044715f * x * x * x);
        t1[i] = 0.5f * x * (1.0f + tanhf(inner));
    }
}

// ---------------- combine: out = x1 + sum_k gate_k * (keep ? eout[e,p] : h2) ----------------
__global__ void combine_kernel(const float* __restrict__ x1, const float* __restrict__ h2,
                               const float* __restrict__ eout, const float* __restrict__ gate,
                               const int* __restrict__ expert, const int* __restrict__ slot,
                               const int* __restrict__ keep, float* __restrict__ out) {
    int n = blockIdx.x;
    int tid = threadIdx.x;
    float g0 = gate[n * 2], g1 = gate[n * 2 + 1];
    const float* s0 = keep[n * 2]
        ? eout + ((long long)expert[n * 2] * CAP + slot[n * 2]) * DD
        : h2 + (long long)n * DD;
    const float* s1 = keep[n * 2 + 1]
        ? eout + ((long long)expert[n * 2 + 1] * CAP + slot[n * 2 + 1]) * DD
        : h2 + (long long)n * DD;
    const float* xr = x1 + (long long)n * DD;
    float* o = out + (long long)n * DD;
    for (int d = tid; d < DD; d += 256)
        o[d] = xr[d] + g0 * s0[d] + g1 * s1[d];
}

// ---------------- host launch ----------------
template <typename T>
static T* sym_addr(const void* sym) {
    void* p = nullptr;
    cudaGetSymbolAddress(&p, sym);
    return (T*)p;
}

extern "C" void kernel_launch(void* const* d_in, const int* in_sizes, int n_in,
                              void* d_out, int out_size) {
    const float* x      = (const float*)d_in[0];
    const float* wq     = (const float*)d_in[1];
    const float* wk     = (const float*)d_in[2];
    const float* wv     = (const float*)d_in[3];
    const float* wo     = (const float*)d_in[4];
    const float* rw     = (const float*)d_in[5];
    const float* rb     = (const float*)d_in[6];
    const float* w1     = (const float*)d_in[7];
    const float* w2     = (const float*)d_in[8];
    const float* w3     = (const float*)d_in[9];
    const float* n1s    = (const float*)d_in[10];
    const float* n2s    = (const float*)d_in[11];
    float* out = (float*)d_out;

    float* ph    = sym_addr<float>(g_h);
    float* pq    = sym_addr<float>(g_q);
    float* pk    = sym_addr<float>(g_k);
    float* pv    = sym_addr<float>(g_v);
    float* pattn = sym_addr<float>(g_attn);
    float* px1   = sym_addr<float>(g_x1);
    float* ph2   = sym_addr<float>(g_h2);
    float* pgate = sym_addr<float>(g_gate);
    int*   pexp  = sym_addr<int>(g_expert);
    int*   pslot = sym_addr<int>(g_slot);
    int*   pkeep = sym_addr<int>(g_keep);
    float* pgrp  = sym_addr<float>(g_grouped);
    float* pt1   = sym_addr<float>(g_t1);
    float* pt2   = sym_addr<float>(g_t2);
    float* peout = sym_addr<float>(g_eout);

    // ---- attention path ----
    rmsnorm_kernel<<<NTOK, 256>>>(x, n1s, ph);
    sgemm128<<<dim3(1024 / 128, NTOK / 128, 1), 256>>>(ph, wq, pq, nullptr, NTOK, 1024, DD, 0, 0, 0);
    sgemm128<<<dim3(256 / 128,  NTOK / 128, 1), 256>>>(ph, wk, pk, nullptr, NTOK, 256,  DD, 0, 0, 0);
    sgemm128<<<dim3(256 / 128,  NTOK / 128, 1), 256>>>(ph, wv, pv, nullptr, NTOK, 256,  DD, 0, 0, 0);
    {
        long long tq = (long long)NTOK * HQ * 32;
        rope_kernel<<<(int)((tq + 255) / 256), 256>>>(pq, HQ, tq);
        long long tk = (long long)NTOK * HKV * 32;
        rope_kernel<<<(int)((tk + 255) / 256), 256>>>(pk, HKV, tk);
    }
    attn_kernel<<<dim3(TT, HQ, BB), 128>>>(pq, pk, pv, pattn);
    sgemm128<<<dim3(1024 / 128, NTOK / 128, 1), 256>>>(pattn, wo, px1, x, NTOK, DD, HQ * VD, 0, 0, 0);

    // ---- MoE path ----
    rmsnorm_kernel<<<NTOK, 256>>>(px1, n2s, ph2);
    router_kernel<<<NTOK, 128>>>(ph2, rw, rb, pgate, pexp);
    capacity_kernel<<<1, 256>>>(pexp, pslot, pkeep);
    zero_kernel<<<1024, 256>>>(pgrp, (long long)EE * CAP * DD);
    dispatch_kernel<<<NTOK * TOPK, 256>>>(ph2, pexp, pslot, pkeep, pgrp);
    sgemm128<<<dim3(HID / 128, CAP / 128, EE), 256>>>(pgrp, w1, pt1, nullptr,
        CAP, HID, DD, (long long)CAP * DD, (long long)DD * HID, (long long)CAP * HID);
    sgemm128<<<dim3(HID / 128, CAP / 128, EE), 256>>>(pgrp, w2, pt2, nullptr,
        CAP, HID, DD, (long long)CAP * DD, (long long)DD * HID, (long long)CAP * HID);
    gelu_mul_kernel<<<2048, 256>>>(pt1, pt2, (long long)EE * CAP * HID);
    sgemm128<<<dim3(DD / 128, CAP / 128, EE), 256>>>(pt1, w3, peout, nullptr,
        CAP, DD, HID, (long long)CAP * HID, (long long)HID * DD, (long long)CAP * DD);
    combine_kernel<<<NTOK, 256>>>(px1, ph2, peout, pgate, pexp, pslot, pkeep, out);
}

// round 7
// speedup vs baseline: 1.3501x; 1.3501x over previous
#include <cuda_runtime.h>
#include <cuda_bf16.h>
#include <cstdint>
#include <math.h>

// ---------------- problem constants ----------------
#define BB   2
#define TT   1024
#define DD   1024
#define NTOK (BB*TT)          // 2048
#define HQ   16
#define HKV  4
#define KD   64
#define VD   64
#define EE   8
#define TOPK 2
#define CAP  1024             // floor(2048*0.5)
#define HID  2048
#define EPS  1e-6f

// ---------------- fp32 scratch ----------------
__device__ float g_q   [NTOK*HQ*KD];
__device__ float g_k   [NTOK*HKV*KD];
__device__ float g_v   [NTOK*HKV*VD];
__device__ float g_x1  [NTOK*DD];
__device__ float g_h2  [NTOK*DD];
__device__ float g_gate[NTOK*TOPK];
__device__ int   g_expert[NTOK*TOPK];
__device__ int   g_slot  [NTOK*TOPK];
__device__ int   g_keep  [NTOK*TOPK];
__device__ float g_grouped[EE*CAP*DD];
__device__ float g_t1[EE*CAP*HID];
__device__ float g_t2[EE*CAP*HID];
__device__ float g_eout[EE*CAP*DD];

// ---------------- bf16 split activations (hi/lo) ----------------
__device__ __nv_bfloat16 g_hh [NTOK*DD],     g_hl [NTOK*DD];      // rmsnorm1 out
__device__ __nv_bfloat16 g_ath[NTOK*HQ*VD],  g_atl[NTOK*HQ*VD];   // attn out
__device__ __nv_bfloat16 g_grph[EE*CAP*DD],  g_grpl[EE*CAP*DD];   // dispatched
__device__ __nv_bfloat16 g_t1h[EE*CAP*HID],  g_t1l[EE*CAP*HID];   // gelu out

// ---------------- bf16 split transposed weights [N][K] ----------------
__device__ __nv_bfloat16 g_wqh[DD*DD],      g_wql[DD*DD];
__device__ __nv_bfloat16 g_wkh[256*DD],     g_wkl[256*DD];
__device__ __nv_bfloat16 g_wvh[256*DD],     g_wvl[256*DD];
__device__ __nv_bfloat16 g_woh[DD*DD],      g_wol[DD*DD];
__device__ __nv_bfloat16 g_w1h[EE*HID*DD],  g_w1l[EE*HID*DD];
__device__ __nv_bfloat16 g_w2h[EE*HID*DD],  g_w2l[EE*HID*DD];
__device__ __nv_bfloat16 g_w3h[EE*DD*HID],  g_w3l[EE*DD*HID];

// ================= PTX helpers =================
__device__ __forceinline__ uint32_t smem_u32(const void* p) {
    uint32_t a;
    asm("{ .reg .u64 t; cvta.to.shared.u64 t, %1; cvt.u32.u64 %0, t; }" : "=r"(a) : "l"(p));
    return a;
}
__device__ __forceinline__ void cp16(uint32_t dst, const void* src) {
    asm volatile("cp.async.ca.shared.global [%0], [%1], 16;" :: "r"(dst), "l"(src) : "memory");
}
#define CP_COMMIT() asm volatile("cp.async.commit_group;" ::: "memory")
#define CP_WAIT(n)  asm volatile("cp.async.wait_group %0;" :: "n"(n) : "memory")

#define LDSM4(r0, r1, r2, r3, addr) \
    asm volatile("ldmatrix.sync.aligned.m8n8.x4.shared.b16 {%0,%1,%2,%3}, [%4];" \
        : "=r"(r0), "=r"(r1), "=r"(r2), "=r"(r3) : "r"(addr))

#define MMA_BF16(d, a, b) \
    asm volatile("mma.sync.aligned.m16n8k16.row.col.f32.bf16.bf16.f32 " \
        "{%0,%1,%2,%3}, {%4,%5,%6,%7}, {%8,%9}, {%0,%1,%2,%3};" \
        : "+f"((d)[0]), "+f"((d)[1]), "+f"((d)[2]), "+f"((d)[3]) \
        : "r"((a)[0]), "r"((a)[1]), "r"((a)[2]), "r"((a)[3]), \
          "r"((b)[0]), "r"((b)[1]))

// ================= split-bf16 HMMA GEMM =================
// C[M,N] (+Res) = A[M,K] * Bt[N,K]^T, A/B given as (hi,lo) bf16 pairs.
// CTA tile 128x128, BK=32 double-buffered cp.async, 8 warps of 64x32.
// 3 MMA terms (hh, hl, lh) accumulate into the same fp32 registers.
// smem stage: Ah[128x64B] | Al | Bh | Bl  (32KB/stage, 2 stages)
#define STAGE_BYTES 32768

__device__ __forceinline__ void hmma_compute_stage(
    uint32_t sb, int lane, int m0w, int n0w, float acc[4][4][4])
{
#pragma unroll
    for (int s = 0; s < 2; s++) {
        uint32_t ah[4][4], al[4][4], bh[4][2], bl[4][2];
#pragma unroll
        for (int mi = 0; mi < 4; mi++) {
            int row = m0w + mi * 16 + (lane & 15);
            int j = s * 2 + (lane >> 4);
            uint32_t ad = sb + row * 64 + ((j ^ (row & 3)) << 4);
            LDSM4(ah[mi][0], ah[mi][1], ah[mi][2], ah[mi][3], ad);
            LDSM4(al[mi][0], al[mi][1], al[mi][2], al[mi][3], ad + 8192);
        }
#pragma unroll
        for (int np = 0; np < 2; np++) {
            int q = lane >> 3;
            int row = n0w + np * 16 + ((q >> 1) << 3) + (lane & 7);
            int j = s * 2 + (q & 1);
            uint32_t bd = sb + 16384 + row * 64 + ((j ^ (row & 3)) << 4);
            LDSM4(bh[2 * np][0], bh[2 * np][1], bh[2 * np + 1][0], bh[2 * np + 1][1], bd);
            LDSM4(bl[2 * np][0], bl[2 * np][1], bl[2 * np + 1][0], bl[2 * np + 1][1], bd + 8192);
        }
#pragma unroll
        for (int mi = 0; mi < 4; mi++) {
#pragma unroll
            for (int ni = 0; ni < 4; ni++) {
                MMA_BF16(acc[mi][ni], ah[mi], bh[ni]);
                MMA_BF16(acc[mi][ni], ah[mi], bl[ni]);
                MMA_BF16(acc[mi][ni], al[mi], bh[ni]);
            }
        }
    }
}

__global__ __launch_bounds__(256, 1)
void hmma_gemm(const __nv_bfloat16* __restrict__ Ah, const __nv_bfloat16* __restrict__ Al,
               const __nv_bfloat16* __restrict__ Bh, const __nv_bfloat16* __restrict__ Bl,
               float* __restrict__ C, const float* __restrict__ Res,
               int N, int K,
               long long sA, long long sB, long long sC)
{
    extern __shared__ char sm[];
    Ah += (long long)blockIdx.z * sA; Al += (long long)blockIdx.z * sA;
    Bh += (long long)blockIdx.z * sB; Bl += (long long)blockIdx.z * sB;
    C  += (long long)blockIdx.z * sC;

    const int tid = threadIdx.x, wid = tid >> 5, lane = tid & 31;
    const int rowBase = blockIdx.y * 128;
    const int colBase = blockIdx.x * 128;
    const int m0w = (wid >> 2) * 64, n0w = (wid & 3) * 32;
    uint32_t smb = smem_u32(sm);

    float acc[4][4][4];
#pragma unroll
    for (int mi = 0; mi < 4; mi++)
#pragma unroll
        for (int ni = 0; ni < 4; ni++)
#pragma unroll
            for (int r = 0; r < 4; r++) acc[mi][ni][r] = 0.f;

    const int KC = K >> 5;

    // prologue: load stage 0
    {
        uint32_t sb = smb;
#pragma unroll
        for (int p = 0; p < 2; p++) {
            int idx = tid + p * 256;
            int r = idx >> 2, j = idx & 3;
            uint32_t so = r * 64 + ((j ^ (r & 3)) << 4);
            long long ga = (long long)(rowBase + r) * K + j * 8;
            long long gb = (long long)(colBase + r) * K + j * 8;
            cp16(sb + so,         Ah + ga);
            cp16(sb + 8192 + so,  Al + ga);
            cp16(sb + 16384 + so, Bh + gb);
            cp16(sb + 24576 + so, Bl + gb);
        }
        CP_COMMIT();
    }

    for (int c = 0; c < KC; c++) {
        if (c + 1 < KC) {
            uint32_t sb = smb + ((c + 1) & 1) * STAGE_BYTES;
            long long k0 = (long long)(c + 1) * 32;
#pragma unroll
            for (int p = 0; p < 2; p++) {
                int idx = tid + p * 256;
                int r = idx >> 2, j = idx & 3;
                uint32_t so = r * 64 + ((j ^ (r & 3)) << 4);
                long long ga = (long long)(rowBase + r) * K + k0 + j * 8;
                long long gb = (long long)(colBase + r) * K + k0 + j * 8;
                cp16(sb + so,         Ah + ga);
                cp16(sb + 8192 + so,  Al + ga);
                cp16(sb + 16384 + so, Bh + gb);
                cp16(sb + 24576 + so, Bl + gb);
            }
            CP_COMMIT();
            CP_WAIT(1);
        } else {
            CP_WAIT(0);
        }
        __syncthreads();
        hmma_compute_stage(smb + (c & 1) * STAGE_BYTES, lane, m0w, n0w, acc);
        __syncthreads();
    }

    // epilogue
#pragma unroll
    for (int mi = 0; mi < 4; mi++) {
#pragma unroll
        for (int ni = 0; ni < 4; ni++) {
            int row = rowBase + m0w + mi * 16 + (lane >> 2);
            int col = colBase + n0w + ni * 8 + (lane & 3) * 2;
            float2 v0 = make_float2(acc[mi][ni][0], acc[mi][ni][1]);
            float2 v1 = make_float2(acc[mi][ni][2], acc[mi][ni][3]);
            long long o0 = (long long)row * N + col;
            long long o1 = (long long)(row + 8) * N + col;
            if (Res) {
                float2 r0 = *(const float2*)&Res[o0];
                float2 r1 = *(const float2*)&Res[o1];
                v0.x += r0.x; v0.y += r0.y;
                v1.x += r1.x; v1.y += r1.y;
            }
            *(float2*)&C[o0] = v0;
            *(float2*)&C[o1] = v1;
        }
    }
}

// ================= prepack kernels =================
__device__ __forceinline__ void split1(float v, __nv_bfloat16& h, __nv_bfloat16& l) {
    h = __float2bfloat16(v);
    l = __float2bfloat16(v - __bfloat162float(h));
}

// transpose + split: W [K][N] (batched) -> Th/Tl [N][K]
__global__ void tsplit_kernel(const float* __restrict__ W,
                              __nv_bfloat16* __restrict__ Th, __nv_bfloat16* __restrict__ Tl,
                              int K, int N, long long sW, long long sT) {
    __shared__ float tile[32][33];
    W  += (long long)blockIdx.z * sW;
    Th += (long long)blockIdx.z * sT;
    Tl += (long long)blockIdx.z * sT;
    int n0 = blockIdx.x * 32, k0 = blockIdx.y * 32;
    int tx = threadIdx.x, ty = threadIdx.y;
    for (int i = ty; i < 32; i += 8)
        tile[i][tx] = W[(long long)(k0 + i) * N + n0 + tx];
    __syncthreads();
    for (int i = ty; i < 32; i += 8) {
        float v = tile[tx][i];  // W[k0+tx][n0+i]
        __nv_bfloat16 h, l; split1(v, h, l);
        long long o = (long long)(n0 + i) * K + k0 + tx;
        Th[o] = h; Tl[o] = l;
    }
}

__global__ void split_kernel(const float* __restrict__ X,
                             __nv_bfloat16* __restrict__ H, __nv_bfloat16* __restrict__ L,
                             long long n) {
    long long i = (long long)blockIdx.x * blockDim.x + threadIdx.x;
    long long stride = (long long)gridDim.x * blockDim.x;
    for (; i < n; i += stride) {
        __nv_bfloat16 h, l; split1(X[i], h, l);
        H[i] = h; L[i] = l;
    }
}

// gelu(t1*t2) -> split bf16 (tanh approx, jax default)
__global__ void gelu_split_kernel(const float* __restrict__ t1, const float* __restrict__ t2,
                                  __nv_bfloat16* __restrict__ H, __nv_bfloat16* __restrict__ L,
                                  long long n) {
    long long i = (long long)blockIdx.x * blockDim.x + threadIdx.x;
    long long stride = (long long)gridDim.x * blockDim.x;
    for (; i < n; i += stride) {
        float x = t1[i] * t2[i];
        float inner = 0.7978845608028654f * (x + 0.044715f * x * x * x);
        float g = 0.5f * x * (1.0f + tanhf(inner));
        __nv_bfloat16 h, l; split1(g, h, l);
        H[i] = h; L[i] = l;
    }
}

// ================= rmsnorm =================
__global__ void rmsnorm_kernel(const float* __restrict__ x, const float* __restrict__ scale,
                               float* __restrict__ out) {
    int n = blockIdx.x, tid = threadIdx.x;
    __shared__ float red[256];
    const float* xr = x + (long long)n * DD;
    float ss = 0.f;
    for (int d = tid; d < DD; d += 256) { float v = xr[d]; ss += v * v; }
    red[tid] = ss; __syncthreads();
    for (int s = 128; s > 0; s >>= 1) { if (tid < s) red[tid] += red[tid + s]; __syncthreads(); }
    float inv = rsqrtf(red[0] / (float)DD + EPS);
    float* o = out + (long long)n * DD;
    for (int d = tid; d < DD; d += 256) o[d] = xr[d] * inv * scale[d];
}

__global__ void rmsnorm_split_kernel(const float* __restrict__ x, const float* __restrict__ scale,
                                     __nv_bfloat16* __restrict__ oh, __nv_bfloat16* __restrict__ ol) {
    int n = blockIdx.x, tid = threadIdx.x;
    __shared__ float red[256];
    const float* xr = x + (long long)n * DD;
    float ss = 0.f;
    for (int d = tid; d < DD; d += 256) { float v = xr[d]; ss += v * v; }
    red[tid] = ss; __syncthreads();
    for (int s = 128; s > 0; s >>= 1) { if (tid < s) red[tid] += red[tid + s]; __syncthreads(); }
    float inv = rsqrtf(red[0] / (float)DD + EPS);
    for (int d = tid; d < DD; d += 256) {
        float o = xr[d] * inv * scale[d];
        __nv_bfloat16 h, l; split1(o, h, l);
        oh[(long long)n * DD + d] = h;
        ol[(long long)n * DD + d] = l;
    }
}

// ================= rope (in-place) =================
__global__ void rope_kernel(float* __restrict__ data, int H, long long total) {
    long long i = (long long)blockIdx.x * blockDim.x + threadIdx.x;
    if (i >= total) return;
    int half = (int)(i & 31);
    long long nh = i >> 5;
    long long tok = nh / H;
    int t = (int)(tok % TT);
    float theta = __powf(10000.0f, -(float)(2 * half) / 64.0f);
    float ang = (float)t * theta;
    float s = sinf(ang), c = cosf(ang);
    float* p = data + nh * 64;
    float x1 = p[half], x2 = p[half + 32];
    p[half]      = x1 * c - x2 * s;
    p[half + 32] = x2 * c + x1 * s;
}

// ================= attention (fp32, writes split-bf16 output) =================
__global__ __launch_bounds__(128)
void attn_kernel(const float* __restrict__ q, const float* __restrict__ k,
                 const float* __restrict__ v,
                 __nv_bfloat16* __restrict__ oh, __nv_bfloat16* __restrict__ ol) {
    int t = blockIdx.x, hq = blockIdx.y, b = blockIdx.z;
    int kv = hq >> 2;
    __shared__ float qs[64];
    __shared__ float sc[TT];
    __shared__ float red[128];
    int tid = threadIdx.x;
    const float* qp = q + ((long long)(b * TT + t) * HQ + hq) * 64;
    if (tid < 64) qs[tid] = qp[tid];
    __syncthreads();
    int L = t + 1;
    float lmax = -1e30f;
    for (int s = tid; s < L; s += 128) {
        const float* kp = k + ((long long)(b * TT + s) * HKV + kv) * 64;
        float dot = 0.f;
#pragma unroll
        for (int j = 0; j < 64; j++) dot += qs[j] * kp[j];
        dot *= 0.125f;
        sc[s] = dot;
        lmax = fmaxf(lmax, dot);
    }
    red[tid] = lmax; __syncthreads();
    for (int s = 64; s > 0; s >>= 1) { if (tid < s) red[tid] = fmaxf(red[tid], red[tid + s]); __syncthreads(); }
    float m = red[0]; __syncthreads();
    float lsum = 0.f;
    for (int s = tid; s < L; s += 128) { float e = expf(sc[s] - m); sc[s] = e; lsum += e; }
    red[tid] = lsum; __syncthreads();
    for (int s = 64; s > 0; s >>= 1) { if (tid < s) red[tid] += red[tid + s]; __syncthreads(); }
    float inv = 1.0f / red[0];
    if (tid < 64) {
        float acc = 0.f;
        const float* vb = v + ((long long)(b * TT) * HKV + kv) * 64 + tid;
        for (int s = 0; s < L; s++) acc += sc[s] * vb[(long long)s * HKV * 64];
        float o = acc * inv;
        long long idx = ((long long)(b * TT + t) * HQ + hq) * 64 + tid;
        __nv_bfloat16 h, l; split1(o, h, l);
        oh[idx] = h; ol[idx] = l;
    }
}

// ================= router / capacity / dispatch / combine =================
__global__ void router_kernel(const float* __restrict__ h2, const float* __restrict__ rw,
                              const float* __restrict__ rb,
                              float* __restrict__ gate, int* __restrict__ expert) {
    int n = blockIdx.x, tid = threadIdx.x;
    __shared__ float part[128][8];
    float acc[8];
#pragma unroll
    for (int e = 0; e < 8; e++) acc[e] = 0.f;
    const float* xr = h2 + (long long)n * DD;
    for (int d = tid; d < DD; d += 128) {
        float xv = xr[d];
#pragma unroll
        for (int e = 0; e < 8; e++) acc[e] += xv * rw[d * 8 + e];
    }
#pragma unroll
    for (int e = 0; e < 8; e++) part[tid][e] = acc[e];
    __syncthreads();
    if (tid < 8) {
        float s = rb[tid];
        for (int i = 0; i < 128; i++) s += part[i][tid];
        part[0][tid] = s;
    }
    __syncthreads();
    if (tid == 0) {
        float lg[8];
#pragma unroll
        for (int e = 0; e < 8; e++) lg[e] = part[0][e];
        int i0 = 0;
        for (int e = 1; e < 8; e++) if (lg[e] > lg[i0]) i0 = e;
        int i1 = -1;
        for (int e = 0; e < 8; e++) {
            if (e == i0) continue;
            if (i1 < 0 || lg[e] > lg[i1]) i1 = e;
        }
        float a = lg[i0], bq = lg[i1];
        float ea = 1.0f, eb = expf(bq - a);
        float s = ea + eb;
        gate[n * 2] = ea / s; gate[n * 2 + 1] = eb / s;
        expert[n * 2] = i0;   expert[n * 2 + 1] = i1;
    }
}

__global__ void capacity_kernel(const int* __restrict__ expert,
                                int* __restrict__ slot, int* __restrict__ keep) {
    int w = threadIdx.x >> 5;
    int lane = threadIdx.x & 31;
    if (w >= EE) return;
    int c0 = 0, c1 = 0;
    unsigned le = 0xffffffffu >> (31 - lane);
    for (int base = 0; base < NTOK; base += 32) {
        int n = base + lane;
        int e0 = expert[n * 2], e1 = expert[n * 2 + 1];
        unsigned m0 = __ballot_sync(0xffffffffu, e0 == w);
        unsigned m1 = __ballot_sync(0xffffffffu, e1 == w);
        int inc0 = __popc(m0 & le);
        int inc1 = __popc(m1 & le);
        if (e0 == w) {
            int p0 = c0 + inc0;
            keep[n * 2] = (p0 < CAP) ? 1 : 0;
            slot[n * 2] = p0;
        }
        if (e1 == w) {
            int p1 = c0 + inc0 + c1 + inc1;
            keep[n * 2 + 1] = (p1 < CAP) ? 1 : 0;
            slot[n * 2 + 1] = p1;
        }
        c0 += __popc(m0); c1 += __popc(m1);
    }
}

__global__ void dispatch_kernel(const float* __restrict__ h2, const int* __restrict__ expert,
                                const int* __restrict__ slot, const int* __restrict__ keep,
                                float* __restrict__ grouped) {
    int idx = blockIdx.x;
    if (!keep[idx]) return;
    int n = idx >> 1;
    int e = expert[idx], p = slot[idx];
    float* dst = grouped + ((long long)e * CAP + p) * DD;
    const float* src = h2 + (long long)n * DD;
    for (int d = threadIdx.x; d < DD; d += blockDim.x) atomicAdd(&dst[d], src[d]);
}

__global__ void combine_kernel(const float* __restrict__ x1, const float* __restrict__ h2,
                               const float* __restrict__ eout, const float* __restrict__ gate,
                               const int* __restrict__ expert, const int* __restrict__ slot,
                               const int* __restrict__ keep, float* __restrict__ out) {
    int n = blockIdx.x, tid = threadIdx.x;
    float g0 = gate[n * 2], g1 = gate[n * 2 + 1];
    const float* s0 = keep[n * 2]
        ? eout + ((long long)expert[n * 2] * CAP + slot[n * 2]) * DD
        : h2 + (long long)n * DD;
    const float* s1 = keep[n * 2 + 1]
        ? eout + ((long long)expert[n * 2 + 1] * CAP + slot[n * 2 + 1]) * DD
        : h2 + (long long)n * DD;
    const float* xr = x1 + (long long)n * DD;
    float* o = out + (long long)n * DD;
    for (int d = tid; d < DD; d += 256)
        o[d] = xr[d] + g0 * s0[d] + g1 * s1[d];
}

// ================= host launch =================
template <typename T>
static T* sym_addr(const void* sym) {
    void* p = nullptr;
    cudaGetSymbolAddress(&p, sym);
    return (T*)p;
}

#define HM_SMEM (2 * STAGE_BYTES)

extern "C" void kernel_launch(void* const* d_in, const int* in_sizes, int n_in,
                              void* d_out, int out_size) {
    const float* x   = (const float*)d_in[0];
    const float* wq  = (const float*)d_in[1];
    const float* wk  = (const float*)d_in[2];
    const float* wv  = (const float*)d_in[3];
    const float* wo  = (const float*)d_in[4];
    const float* rw  = (const float*)d_in[5];
    const float* rb  = (const float*)d_in[6];
    const float* w1  = (const float*)d_in[7];
    const float* w2  = (const float*)d_in[8];
    const float* w3  = (const float*)d_in[9];
    const float* n1s = (const float*)d_in[10];
    const float* n2s = (const float*)d_in[11];
    float* out = (float*)d_out;

    cudaFuncSetAttribute(hmma_gemm, cudaFuncAttributeMaxDynamicSharedMemorySize, HM_SMEM);

    float* pq    = sym_addr<float>(g_q);
    float* pk    = sym_addr<float>(g_k);
    float* pv    = sym_addr<float>(g_v);
    float* px1   = sym_addr<float>(g_x1);
    float* ph2   = sym_addr<float>(g_h2);
    float* pgate = sym_addr<float>(g_gate);
    int*   pexp  = sym_addr<int>(g_expert);
    int*   pslot = sym_addr<int>(g_slot);
    int*   pkeep = sym_addr<int>(g_keep);
    float* pgrp  = sym_addr<float>(g_grouped);
    float* pt1   = sym_addr<float>(g_t1);
    float* pt2   = sym_addr<float>(g_t2);
    float* peout = sym_addr<float>(g_eout);

    __nv_bfloat16* phh  = sym_addr<__nv_bfloat16>(g_hh);
    __nv_bfloat16* phl  = sym_addr<__nv_bfloat16>(g_hl);
    __nv_bfloat16* path = sym_addr<__nv_bfloat16>(g_ath);
    __nv_bfloat16* patl = sym_addr<__nv_bfloat16>(g_atl);
    __nv_bfloat16* pgh  = sym_addr<__nv_bfloat16>(g_grph);
    __nv_bfloat16* pgl  = sym_addr<__nv_bfloat16>(g_grpl);
    __nv_bfloat16* pt1h = sym_addr<__nv_bfloat16>(g_t1h);
    __nv_bfloat16* pt1l = sym_addr<__nv_bfloat16>(g_t1l);

    __nv_bfloat16* pwqh = sym_addr<__nv_bfloat16>(g_wqh);
    __nv_bfloat16* pwql = sym_addr<__nv_bfloat16>(g_wql);
    __nv_bfloat16* pwkh = sym_addr<__nv_bfloat16>(g_wkh);
    __nv_bfloat16* pwkl = sym_addr<__nv_bfloat16>(g_wkl);
    __nv_bfloat16* pwvh = sym_addr<__nv_bfloat16>(g_wvh);
    __nv_bfloat16* pwvl = sym_addr<__nv_bfloat16>(g_wvl);
    __nv_bfloat16* pwoh = sym_addr<__nv_bfloat16>(g_woh);
    __nv_bfloat16* pwol = sym_addr<__nv_bfloat16>(g_wol);
    __nv_bfloat16* pw1h = sym_addr<__nv_bfloat16>(g_w1h);
    __nv_bfloat16* pw1l = sym_addr<__nv_bfloat16>(g_w1l);
    __nv_bfloat16* pw2h = sym_addr<__nv_bfloat16>(g_w2h);
    __nv_bfloat16* pw2l = sym_addr<__nv_bfloat16>(g_w2l);
    __nv_bfloat16* pw3h = sym_addr<__nv_bfloat16>(g_w3h);
    __nv_bfloat16* pw3l = sym_addr<__nv_bfloat16>(g_w3l);

    dim3 tb(32, 8);
    // ---- weight prepack (transpose + hi/lo split) ----
    tsplit_kernel<<<dim3(DD / 32, DD / 32, 1), tb>>>(wq, pwqh, pwql, DD, DD, 0, 0);
    tsplit_kernel<<<dim3(256 / 32, DD / 32, 1), tb>>>(wk, pwkh, pwkl, DD, 256, 0, 0);
    tsplit_kernel<<<dim3(256 / 32, DD / 32, 1), tb>>>(wv, pwvh, pwvl, DD, 256, 0, 0);
    tsplit_kernel<<<dim3(DD / 32, DD / 32, 1), tb>>>(wo, pwoh, pwol, DD, DD, 0, 0);
    tsplit_kernel<<<dim3(HID / 32, DD / 32, EE), tb>>>(w1, pw1h, pw1l, DD, HID,
        (long long)DD * HID, (long long)DD * HID);
    tsplit_kernel<<<dim3(HID / 32, DD / 32, EE), tb>>>(w2, pw2h, pw2l, DD, HID,
        (long long)DD * HID, (long long)DD * HID);
    tsplit_kernel<<<dim3(DD / 32, HID / 32, EE), tb>>>(w3, pw3h, pw3l, HID, DD,
        (long long)HID * DD, (long long)HID * DD);

    // ---- attention path ----
    rmsnorm_split_kernel<<<NTOK, 256>>>(x, n1s, phh, phl);
    hmma_gemm<<<dim3(8, 16, 1), 256, HM_SMEM>>>(phh, phl, pwqh, pwql, pq, nullptr, 1024, DD, 0, 0, 0);
    hmma_gemm<<<dim3(2, 16, 1), 256, HM_SMEM>>>(phh, phl, pwkh, pwkl, pk, nullptr, 256, DD, 0, 0, 0);
    hmma_gemm<<<dim3(2, 16, 1), 256, HM_SMEM>>>(phh, phl, pwvh, pwvl, pv, nullptr, 256, DD, 0, 0, 0);
    {
        long long tq = (long long)NTOK * HQ * 32;
        rope_kernel<<<(int)((tq + 255) / 256), 256>>>(pq, HQ, tq);
        long long tk = (long long)NTOK * HKV * 32;
        rope_kernel<<<(int)((tk + 255) / 256), 256>>>(pk, HKV, tk);
    }
    attn_kernel<<<dim3(TT, HQ, BB), 128>>>(pq, pk, pv, path, patl);
    hmma_gemm<<<dim3(8, 16, 1), 256, HM_SMEM>>>(path, patl, pwoh, pwol, px1, x, 1024, HQ * VD, 0, 0, 0);

    // ---- MoE path ----
    rmsnorm_kernel<<<NTOK, 256>>>(px1, n2s, ph2);
    router_kernel<<<NTOK, 128>>>(ph2, rw, rb, pgate, pexp);
    capacity_kernel<<<1, 256>>>(pexp, pslot, pkeep);
    cudaMemsetAsync(pgrp, 0, (size_t)EE * CAP * DD * sizeof(float));
    dispatch_kernel<<<NTOK * TOPK, 256>>>(ph2, pexp, pslot, pkeep, pgrp);
    split_kernel<<<2048, 256>>>(pgrp, pgh, pgl, (long long)EE * CAP * DD);

    hmma_gemm<<<dim3(HID / 128, CAP / 128, EE), 256, HM_SMEM>>>(pgh, pgl, pw1h, pw1l, pt1, nullptr,
        HID, DD, (long long)CAP * DD, (long long)DD * HID, (long long)CAP * HID);
    hmma_gemm<<<dim3(HID / 128, CAP / 128, EE), 256, HM_SMEM>>>(pgh, pgl, pw2h, pw2l, pt2, nullptr,
        HID, DD, (long long)CAP * DD, (long long)DD * HID, (long long)CAP * HID);
    gelu_split_kernel<<<2048, 256>>>(pt1, pt2, pt1h, pt1l, (long long)EE * CAP * HID);
    hmma_gemm<<<dim3(DD / 128, CAP / 128, EE), 256, HM_SMEM>>>(pt1h, pt1l, pw3h, pw3l, peout, nullptr,
        DD, HID, (long long)CAP * HID, (long long)HID * DD, (long long)CAP * DD);
    combine_kernel<<<NTOK, 256>>>(px1, ph2, peout, pgate, pexp, pslot, pkeep, out);
}

// round 8
// speedup vs baseline: 3.3258x; 2.4634x over previous
#include <cuda_runtime.h>
#include <cuda_bf16.h>
#include <cstdint>
#include <math.h>

// ---------------- problem constants ----------------
#define BB   2
#define TT   1024
#define DD   1024
#define NTOK (BB*TT)          // 2048
#define HQ   16
#define HKV  4
#define KD   64
#define VD   64
#define EE   8
#define TOPK 2
#define CAP  1024             // floor(2048*0.5)
#define HID  2048
#define EPS  1e-6f
#define QKVN 1536             // 1024 q + 256 k + 256 v

// ---------------- fp32 scratch ----------------
__device__ float g_qkv [NTOK*QKVN];      // fused q|k|v projection out
__device__ float g_x1  [NTOK*DD];
__device__ float g_h2  [NTOK*DD];
__device__ float g_gate[NTOK*TOPK];
__device__ int   g_expert[NTOK*TOPK];
__device__ int   g_slot  [NTOK*TOPK];
__device__ int   g_keep  [NTOK*TOPK];
__device__ float g_grouped[EE*CAP*DD];
__device__ float g_t12[EE*CAP*2*HID];    // fused w1|w2 out
__device__ float g_eout[EE*CAP*DD];

// ---------------- bf16 split activations (hi/lo) ----------------
__device__ __nv_bfloat16 g_hh [NTOK*DD],     g_hl [NTOK*DD];      // rmsnorm1 out
__device__ __nv_bfloat16 g_ath[NTOK*HQ*VD],  g_atl[NTOK*HQ*VD];   // attn out
__device__ __nv_bfloat16 g_grph[EE*CAP*DD],  g_grpl[EE*CAP*DD];   // dispatched
__device__ __nv_bfloat16 g_t1h[EE*CAP*HID],  g_t1l[EE*CAP*HID];   // gelu out

// ---------------- bf16 split transposed weights [N][K] ----------------
__device__ __nv_bfloat16 g_wqkvh[QKVN*DD],  g_wqkvl[QKVN*DD];     // wq|wk|wv
__device__ __nv_bfloat16 g_woh[DD*DD],      g_wol[DD*DD];
__device__ __nv_bfloat16 g_w12h[EE*2*HID*DD], g_w12l[EE*2*HID*DD]; // w1|w2
__device__ __nv_bfloat16 g_w3h[EE*DD*HID],  g_w3l[EE*DD*HID];

// ================= PTX helpers =================
__device__ __forceinline__ uint32_t smem_u32(const void* p) {
    uint32_t a;
    asm("{ .reg .u64 t; cvta.to.shared.u64 t, %1; cvt.u32.u64 %0, t; }" : "=r"(a) : "l"(p));
    return a;
}
__device__ __forceinline__ void cp16(uint32_t dst, const void* src) {
    asm volatile("cp.async.ca.shared.global [%0], [%1], 16;" :: "r"(dst), "l"(src) : "memory");
}
#define CP_COMMIT() asm volatile("cp.async.commit_group;" ::: "memory")
#define CP_WAIT(n)  asm volatile("cp.async.wait_group %0;" :: "n"(n) : "memory")

#define LDSM4(r0, r1, r2, r3, addr) \
    asm volatile("ldmatrix.sync.aligned.m8n8.x4.shared.b16 {%0,%1,%2,%3}, [%4];" \
        : "=r"(r0), "=r"(r1), "=r"(r2), "=r"(r3) : "r"(addr))

#define MMA_BF16(d, a, b) \
    asm volatile("mma.sync.aligned.m16n8k16.row.col.f32.bf16.bf16.f32 " \
        "{%0,%1,%2,%3}, {%4,%5,%6,%7}, {%8,%9}, {%0,%1,%2,%3};" \
        : "+f"((d)[0]), "+f"((d)[1]), "+f"((d)[2]), "+f"((d)[3]) \
        : "r"((a)[0]), "r"((a)[1]), "r"((a)[2]), "r"((a)[3]), \
          "r"((b)[0]), "r"((b)[1]))

// ================= split-bf16 HMMA GEMM =================
// C[M,N] (+Res) = A[M,K] * Bt[N,K]^T, A/B given as (hi,lo) bf16 pairs.
// CTA tile 128x128, BK=32 double-buffered cp.async, 8 warps of 64x32.
// 3 MMA terms (hh, hl, lh) accumulate into the same fp32 registers.
#define STAGE_BYTES 32768

__device__ __forceinline__ void hmma_compute_stage(
    uint32_t sb, int lane, int m0w, int n0w, float acc[4][4][4])
{
#pragma unroll
    for (int s = 0; s < 2; s++) {
        uint32_t ah[4][4], al[4][4], bh[4][2], bl[4][2];
#pragma unroll
        for (int mi = 0; mi < 4; mi++) {
            int row = m0w + mi * 16 + (lane & 15);
            int j = s * 2 + (lane >> 4);
            uint32_t ad = sb + row * 64 + ((j ^ (row & 3)) << 4);
            LDSM4(ah[mi][0], ah[mi][1], ah[mi][2], ah[mi][3], ad);
            LDSM4(al[mi][0], al[mi][1], al[mi][2], al[mi][3], ad + 8192);
        }
#pragma unroll
        for (int np = 0; np < 2; np++) {
            int q = lane >> 3;
            int row = n0w + np * 16 + ((q >> 1) << 3) + (lane & 7);
            int j = s * 2 + (q & 1);
            uint32_t bd = sb + 16384 + row * 64 + ((j ^ (row & 3)) << 4);
            LDSM4(bh[2 * np][0], bh[2 * np][1], bh[2 * np + 1][0], bh[2 * np + 1][1], bd);
            LDSM4(bl[2 * np][0], bl[2 * np][1], bl[2 * np + 1][0], bl[2 * np + 1][1], bd + 8192);
        }
#pragma unroll
        for (int mi = 0; mi < 4; mi++) {
#pragma unroll
            for (int ni = 0; ni < 4; ni++) {
                MMA_BF16(acc[mi][ni], ah[mi], bh[ni]);
                MMA_BF16(acc[mi][ni], ah[mi], bl[ni]);
                MMA_BF16(acc[mi][ni], al[mi], bh[ni]);
            }
        }
    }
}

__global__ __launch_bounds__(256, 1)
void hmma_gemm(const __nv_bfloat16* __restrict__ Ah, const __nv_bfloat16* __restrict__ Al,
               const __nv_bfloat16* __restrict__ Bh, const __nv_bfloat16* __restrict__ Bl,
               float* __restrict__ C, const float* __restrict__ Res,
               int N, int K,
               long long sA, long long sB, long long sC)
{
    extern __shared__ char sm[];
    Ah += (long long)blockIdx.z * sA; Al += (long long)blockIdx.z * sA;
    Bh += (long long)blockIdx.z * sB; Bl += (long long)blockIdx.z * sB;
    C  += (long long)blockIdx.z * sC;

    const int tid = threadIdx.x, wid = tid >> 5, lane = tid & 31;
    const int rowBase = blockIdx.y * 128;
    const int colBase = blockIdx.x * 128;
    const int m0w = (wid >> 2) * 64, n0w = (wid & 3) * 32;
    uint32_t smb = smem_u32(sm);

    float acc[4][4][4];
#pragma unroll
    for (int mi = 0; mi < 4; mi++)
#pragma unroll
        for (int ni = 0; ni < 4; ni++)
#pragma unroll
            for (int r = 0; r < 4; r++) acc[mi][ni][r] = 0.f;

    const int KC = K >> 5;

    {
        uint32_t sb = smb;
#pragma unroll
        for (int p = 0; p < 2; p++) {
            int idx = tid + p * 256;
            int r = idx >> 2, j = idx & 3;
            uint32_t so = r * 64 + ((j ^ (r & 3)) << 4);
            long long ga = (long long)(rowBase + r) * K + j * 8;
            long long gb = (long long)(colBase + r) * K + j * 8;
            cp16(sb + so,         Ah + ga);
            cp16(sb + 8192 + so,  Al + ga);
            cp16(sb + 16384 + so, Bh + gb);
            cp16(sb + 24576 + so, Bl + gb);
        }
        CP_COMMIT();
    }

    for (int c = 0; c < KC; c++) {
        if (c + 1 < KC) {
            uint32_t sb = smb + ((c + 1) & 1) * STAGE_BYTES;
            long long k0 = (long long)(c + 1) * 32;
#pragma unroll
            for (int p = 0; p < 2; p++) {
                int idx = tid + p * 256;
                int r = idx >> 2, j = idx & 3;
                uint32_t so = r * 64 + ((j ^ (r & 3)) << 4);
                long long ga = (long long)(rowBase + r) * K + k0 + j * 8;
                long long gb = (long long)(colBase + r) * K + k0 + j * 8;
                cp16(sb + so,         Ah + ga);
                cp16(sb + 8192 + so,  Al + ga);
                cp16(sb + 16384 + so, Bh + gb);
                cp16(sb + 24576 + so, Bl + gb);
            }
            CP_COMMIT();
            CP_WAIT(1);
        } else {
            CP_WAIT(0);
        }
        __syncthreads();
        hmma_compute_stage(smb + (c & 1) * STAGE_BYTES, lane, m0w, n0w, acc);
        __syncthreads();
    }

#pragma unroll
    for (int mi = 0; mi < 4; mi++) {
#pragma unroll
        for (int ni = 0; ni < 4; ni++) {
            int row = rowBase + m0w + mi * 16 + (lane >> 2);
            int col = colBase + n0w + ni * 8 + (lane & 3) * 2;
            float2 v0 = make_float2(acc[mi][ni][0], acc[mi][ni][1]);
            float2 v1 = make_float2(acc[mi][ni][2], acc[mi][ni][3]);
            long long o0 = (long long)row * N + col;
            long long o1 = (long long)(row + 8) * N + col;
            if (Res) {
                float2 r0 = *(const float2*)&Res[o0];
                float2 r1 = *(const float2*)&Res[o1];
                v0.x += r0.x; v0.y += r0.y;
                v1.x += r1.x; v1.y += r1.y;
            }
            *(float2*)&C[o0] = v0;
            *(float2*)&C[o1] = v1;
        }
    }
}

// ================= prepack kernels =================
__device__ __forceinline__ void split1(float v, __nv_bfloat16& h, __nv_bfloat16& l) {
    h = __float2bfloat16(v);
    l = __float2bfloat16(v - __bfloat162float(h));
}

// transpose + split: W [K][N] (batched) -> Th/Tl [N][K]
__global__ void tsplit_kernel(const float* __restrict__ W,
                              __nv_bfloat16* __restrict__ Th, __nv_bfloat16* __restrict__ Tl,
                              int K, int N, long long sW, long long sT) {
    __shared__ float tile[32][33];
    W  += (long long)blockIdx.z * sW;
    Th += (long long)blockIdx.z * sT;
    Tl += (long long)blockIdx.z * sT;
    int n0 = blockIdx.x * 32, k0 = blockIdx.y * 32;
    int tx = threadIdx.x, ty = threadIdx.y;
    for (int i = ty; i < 32; i += 8)
        tile[i][tx] = W[(long long)(k0 + i) * N + n0 + tx];
    __syncthreads();
    for (int i = ty; i < 32; i += 8) {
        float v = tile[tx][i];  // W[k0+tx][n0+i]
        __nv_bfloat16 h, l; split1(v, h, l);
        long long o = (long long)(n0 + i) * K + k0 + tx;
        Th[o] = h; Tl[o] = l;
    }
}

__global__ void split_kernel(const float* __restrict__ X,
                             __nv_bfloat16* __restrict__ H, __nv_bfloat16* __restrict__ L,
                             long long n) {
    long long i = (long long)blockIdx.x * blockDim.x + threadIdx.x;
    long long stride = (long long)gridDim.x * blockDim.x;
    for (; i < n; i += stride) {
        __nv_bfloat16 h, l; split1(X[i], h, l);
        H[i] = h; L[i] = l;
    }
}

// gelu(w1x * w2x) from fused t12 -> split bf16 (tanh approx, jax default)
__global__ void gelu_split_kernel(const float* __restrict__ t12,
                                  __nv_bfloat16* __restrict__ H, __nv_bfloat16* __restrict__ L,
                                  long long n) {
    long long i = (long long)blockIdx.x * blockDim.x + threadIdx.x;
    long long stride = (long long)gridDim.x * blockDim.x;
    for (; i < n; i += stride) {
        long long r = i >> 11;            // /HID
        int hcol = (int)(i & (HID - 1));
        float a = t12[r * (2 * HID) + hcol];
        float b = t12[r * (2 * HID) + HID + hcol];
        float x = a * b;
        float inner = 0.7978845608028654f * (x + 0.044715f * x * x * x);
        float g = 0.5f * x * (1.0f + tanhf(inner));
        __nv_bfloat16 h, l; split1(g, h, l);
        H[i] = h; L[i] = l;
    }
}

// ================= rmsnorm =================
__global__ void rmsnorm_kernel(const float* __restrict__ x, const float* __restrict__ scale,
                               float* __restrict__ out) {
    int n = blockIdx.x, tid = threadIdx.x;
    __shared__ float red[256];
    const float* xr = x + (long long)n * DD;
    float ss = 0.f;
    for (int d = tid; d < DD; d += 256) { float v = xr[d]; ss += v * v; }
    red[tid] = ss; __syncthreads();
    for (int s = 128; s > 0; s >>= 1) { if (tid < s) red[tid] += red[tid + s]; __syncthreads(); }
    float inv = rsqrtf(red[0] / (float)DD + EPS);
    float* o = out + (long long)n * DD;
    for (int d = tid; d < DD; d += 256) o[d] = xr[d] * inv * scale[d];
}

__global__ void rmsnorm_split_kernel(const float* __restrict__ x, const float* __restrict__ scale,
                                     __nv_bfloat16* __restrict__ oh, __nv_bfloat16* __restrict__ ol) {
    int n = blockIdx.x, tid = threadIdx.x;
    __shared__ float red[256];
    const float* xr = x + (long long)n * DD;
    float ss = 0.f;
    for (int d = tid; d < DD; d += 256) { float v = xr[d]; ss += v * v; }
    red[tid] = ss; __syncthreads();
    for (int s = 128; s > 0; s >>= 1) { if (tid < s) red[tid] += red[tid + s]; __syncthreads(); }
    float inv = rsqrtf(red[0] / (float)DD + EPS);
    for (int d = tid; d < DD; d += 256) {
        float o = xr[d] * inv * scale[d];
        __nv_bfloat16 h, l; split1(o, h, l);
        oh[(long long)n * DD + d] = h;
        ol[(long long)n * DD + d] = l;
    }
}

// ================= rope (in-place on fused qkv buffer) =================
// element (tok, h, half) of the section starting at column colOff, H heads
__global__ void rope_kernel(float* __restrict__ qkv, int H, int colOff, long long total) {
    long long i = (long long)blockIdx.x * blockDim.x + threadIdx.x;
    if (i >= total) return;
    int half = (int)(i & 31);
    long long nh = i >> 5;
    int h = (int)(nh % H);
    long long tok = nh / H;
    int t = (int)(tok % TT);
    float theta = __powf(10000.0f, -(float)(2 * half) / 64.0f);
    float ang = (float)t * theta;
    float s = sinf(ang), c = cosf(ang);
    float* p = qkv + tok * QKVN + colOff + h * 64;
    float x1 = p[half], x2 = p[half + 32];
    p[half]      = x1 * c - x2 * s;
    p[half + 32] = x2 * c + x1 * s;
}

// ================= attention =================
// One block per (t, kv_head, batch); processes all G=4 query heads sharing k/v.
// Phase1: warp-per-key shfl-dot (coalesced k loads, 4 heads amortized).
// Phase3: warp-per-key-stride, lane-per-dim coalesced v loads, smem reduce.
__global__ __launch_bounds__(256)
void attn_kernel(const float* __restrict__ qkv,
                 __nv_bfloat16* __restrict__ oh, __nv_bfloat16* __restrict__ ol) {
    int t = blockIdx.x, kvh = blockIdx.y, b = blockIdx.z;
    int tid = threadIdx.x, wid = tid >> 5, lane = tid & 31;
    __shared__ float qs[4][64];
    __shared__ float sc[4][TT];
    __shared__ float wacc[8][4][64];
    __shared__ float red[8][4];
    __shared__ float hmax[4], hinv[4];

    const float* base = qkv + (long long)(b * TT) * QKVN;
    {
        int g = tid >> 6, d = tid & 63;
        qs[g][d] = base[(long long)t * QKVN + (kvh * 4 + g) * 64 + d];
    }
    __syncthreads();

    int L = t + 1;
    const float* kbase = base + 1024 + kvh * 64;
    const float* vbase = base + 1280 + kvh * 64;

    // phase 1: scores + per-head running max (tracked on lane 0)
    float m[4] = {-1e30f, -1e30f, -1e30f, -1e30f};
    for (int s = wid; s < L; s += 8) {
        const float* kr = kbase + (long long)s * QKVN;
        float k0 = kr[lane], k1 = kr[lane + 32];
#pragma unroll
        for (int g = 0; g < 4; g++) {
            float d = qs[g][lane] * k0 + qs[g][lane + 32] * k1;
            d += __shfl_down_sync(0xffffffffu, d, 16);
            d += __shfl_down_sync(0xffffffffu, d, 8);
            d += __shfl_down_sync(0xffffffffu, d, 4);
            d += __shfl_down_sync(0xffffffffu, d, 2);
            d += __shfl_down_sync(0xffffffffu, d, 1);
            if (lane == 0) {
                d *= 0.125f;
                sc[g][s] = d;
                m[g] = fmaxf(m[g], d);
            }
        }
    }
    if (lane == 0) {
#pragma unroll
        for (int g = 0; g < 4; g++) red[wid][g] = m[g];
    }
    __syncthreads();
    if (tid < 4) {
        float mm = -1e30f;
        for (int w = 0; w < 8; w++) mm = fmaxf(mm, red[w][tid]);
        hmax[tid] = mm;
    }
    __syncthreads();

    // phase 2: exp + sums
    float s0 = 0, s1 = 0, s2 = 0, s3 = 0;
    float hm0 = hmax[0], hm1 = hmax[1], hm2 = hmax[2], hm3 = hmax[3];
    for (int s = tid; s < L; s += 256) {
        float e;
        e = expf(sc[0][s] - hm0); sc[0][s] = e; s0 += e;
        e = expf(sc[1][s] - hm1); sc[1][s] = e; s1 += e;
        e = expf(sc[2][s] - hm2); sc[2][s] = e; s2 += e;
        e = expf(sc[3][s] - hm3); sc[3][s] = e; s3 += e;
    }
#pragma unroll
    for (int off = 16; off > 0; off >>= 1) {
        s0 += __shfl_down_sync(0xffffffffu, s0, off);
        s1 += __shfl_down_sync(0xffffffffu, s1, off);
        s2 += __shfl_down_sync(0xffffffffu, s2, off);
        s3 += __shfl_down_sync(0xffffffffu, s3, off);
    }
    __syncthreads();   // sc writes done before reuse of red
    if (lane == 0) { red[wid][0] = s0; red[wid][1] = s1; red[wid][2] = s2; red[wid][3] = s3; }
    __syncthreads();
    if (tid < 4) {
        float ssum = 0;
        for (int w = 0; w < 8; w++) ssum += red[w][tid];
        hinv[tid] = 1.0f / ssum;
    }
    __syncthreads();

    // phase 3: weighted V accumulate (coalesced), smem cross-warp reduce
    float a00 = 0, a01 = 0, a10 = 0, a11 = 0, a20 = 0, a21 = 0, a30 = 0, a31 = 0;
    for (int s = wid; s < L; s += 8) {
        const float* vr = vbase + (long long)s * QKVN;
        float v0 = vr[lane], v1 = vr[lane + 32];
        float w0 = sc[0][s], w1 = sc[1][s], w2 = sc[2][s], w3 = sc[3][s];
        a00 += w0 * v0; a01 += w0 * v1;
        a10 += w1 * v0; a11 += w1 * v1;
        a20 += w2 * v0; a21 += w2 * v1;
        a30 += w3 * v0; a31 += w3 * v1;
    }
    wacc[wid][0][lane] = a00; wacc[wid][0][lane + 32] = a01;
    wacc[wid][1][lane] = a10; wacc[wid][1][lane + 32] = a11;
    wacc[wid][2][lane] = a20; wacc[wid][2][lane + 32] = a21;
    wacc[wid][3][lane] = a30; wacc[wid][3][lane + 32] = a31;
    __syncthreads();
    {
        int g = tid >> 6, d = tid & 63;
        float acc = 0;
#pragma unroll
        for (int w = 0; w < 8; w++) acc += wacc[w][g][d];
        acc *= hinv[g];
        long long idx = ((long long)(b * TT + t) * HQ + kvh * 4 + g) * 64 + d;
        __nv_bfloat16 h, l; split1(acc, h, l);
        oh[idx] = h; ol[idx] = l;
    }
}

// ================= router / capacity / dispatch / combine =================
__global__ void router_kernel(const float* __restrict__ h2, const float* __restrict__ rw,
                              const float* __restrict__ rb,
                              float* __restrict__ gate, int* __restrict__ expert) {
    int n = blockIdx.x, tid = threadIdx.x;
    __shared__ float part[128][8];
    float acc[8];
#pragma unroll
    for (int e = 0; e < 8; e++) acc[e] = 0.f;
    const float* xr = h2 + (long long)n * DD;
    for (int d = tid; d < DD; d += 128) {
        float xv = xr[d];
#pragma unroll
        for (int e = 0; e < 8; e++) acc[e] += xv * rw[d * 8 + e];
    }
#pragma unroll
    for (int e = 0; e < 8; e++) part[tid][e] = acc[e];
    __syncthreads();
    if (tid < 8) {
        float s = rb[tid];
        for (int i = 0; i < 128; i++) s += part[i][tid];
        part[0][tid] = s;
    }
    __syncthreads();
    if (tid == 0) {
        float lg[8];
#pragma unroll
        for (int e = 0; e < 8; e++) lg[e] = part[0][e];
        int i0 = 0;
        for (int e = 1; e < 8; e++) if (lg[e] > lg[i0]) i0 = e;
        int i1 = -1;
        for (int e = 0; e < 8; e++) {
            if (e == i0) continue;
            if (i1 < 0 || lg[e] > lg[i1]) i1 = e;
        }
        float a = lg[i0], bq = lg[i1];
        float ea = 1.0f, eb = expf(bq - a);
        float s = ea + eb;
        gate[n * 2] = ea / s; gate[n * 2 + 1] = eb / s;
        expert[n * 2] = i0;   expert[n * 2 + 1] = i1;
    }
}

__global__ void capacity_kernel(const int* __restrict__ expert,
                                int* __restrict__ slot, int* __restrict__ keep) {
    int w = threadIdx.x >> 5;
    int lane = threadIdx.x & 31;
    if (w >= EE) return;
    int c0 = 0, c1 = 0;
    unsigned le = 0xffffffffu >> (31 - lane);
    for (int base = 0; base < NTOK; base += 32) {
        int n = base + lane;
        int e0 = expert[n * 2], e1 = expert[n * 2 + 1];
        unsigned m0 = __ballot_sync(0xffffffffu, e0 == w);
        unsigned m1 = __ballot_sync(0xffffffffu, e1 == w);
        int inc0 = __popc(m0 & le);
        int inc1 = __popc(m1 & le);
        if (e0 == w) {
            int p0 = c0 + inc0;
            keep[n * 2] = (p0 < CAP) ? 1 : 0;
            slot[n * 2] = p0;
        }
        if (e1 == w) {
            int p1 = c0 + inc0 + c1 + inc1;
            keep[n * 2 + 1] = (p1 < CAP) ? 1 : 0;
            slot[n * 2 + 1] = p1;
        }
        c0 += __popc(m0); c1 += __popc(m1);
    }
}

__global__ void dispatch_kernel(const float* __restrict__ h2, const int* __restrict__ expert,
                                const int* __restrict__ slot, const int* __restrict__ keep,
                                float* __restrict__ grouped) {
    int idx = blockIdx.x;
    if (!keep[idx]) return;
    int n = idx >> 1;
    int e = expert[idx], p = slot[idx];
    float* dst = grouped + ((long long)e * CAP + p) * DD;
    const float* src = h2 + (long long)n * DD;
    for (int d = threadIdx.x; d < DD; d += blockDim.x) atomicAdd(&dst[d], src[d]);
}

__global__ void combine_kernel(const float* __restrict__ x1, const float* __restrict__ h2,
                               const float* __restrict__ eout, const float* __restrict__ gate,
                               const int* __restrict__ expert, const int* __restrict__ slot,
                               const int* __restrict__ keep, float* __restrict__ out) {
    int n = blockIdx.x, tid = threadIdx.x;
    float g0 = gate[n * 2], g1 = gate[n * 2 + 1];
    const float* s0 = keep[n * 2]
        ? eout + ((long long)expert[n * 2] * CAP + slot[n * 2]) * DD
        : h2 + (long long)n * DD;
    const float* s1 = keep[n * 2 + 1]
        ? eout + ((long long)expert[n * 2 + 1] * CAP + slot[n * 2 + 1]) * DD
        : h2 + (long long)n * DD;
    const float* xr = x1 + (long long)n * DD;
    float* o = out + (long long)n * DD;
    for (int d = tid; d < DD; d += 256)
        o[d] = xr[d] + g0 * s0[d] + g1 * s1[d];
}

// ================= host launch =================
template <typename T>
static T* sym_addr(const void* sym) {
    void* p = nullptr;
    cudaGetSymbolAddress(&p, sym);
    return (T*)p;
}

#define HM_SMEM (2 * STAGE_BYTES)

extern "C" void kernel_launch(void* const* d_in, const int* in_sizes, int n_in,
                              void* d_out, int out_size) {
    const float* x   = (const float*)d_in[0];
    const float* wq  = (const float*)d_in[1];
    const float* wk  = (const float*)d_in[2];
    const float* wv  = (const float*)d_in[3];
    const float* wo  = (const float*)d_in[4];
    const float* rw  = (const float*)d_in[5];
    const float* rb  = (const float*)d_in[6];
    const float* w1  = (const float*)d_in[7];
    const float* w2  = (const float*)d_in[8];
    const float* w3  = (const float*)d_in[9];
    const float* n1s = (const float*)d_in[10];
    const float* n2s = (const float*)d_in[11];
    float* out = (float*)d_out;

    cudaFuncSetAttribute(hmma_gemm, cudaFuncAttributeMaxDynamicSharedMemorySize, HM_SMEM);

    float* pqkv  = sym_addr<float>(g_qkv);
    float* px1   = sym_addr<float>(g_x1);
    float* ph2   = sym_addr<float>(g_h2);
    float* pgate = sym_addr<float>(g_gate);
    int*   pexp  = sym_addr<int>(g_expert);
    int*   pslot = sym_addr<int>(g_slot);
    int*   pkeep = sym_addr<int>(g_keep);
    float* pgrp  = sym_addr<float>(g_grouped);
    float* pt12  = sym_addr<float>(g_t12);
    float* peout = sym_addr<float>(g_eout);

    __nv_bfloat16* phh  = sym_addr<__nv_bfloat16>(g_hh);
    __nv_bfloat16* phl  = sym_addr<__nv_bfloat16>(g_hl);
    __nv_bfloat16* path = sym_addr<__nv_bfloat16>(g_ath);
    __nv_bfloat16* patl = sym_addr<__nv_bfloat16>(g_atl);
    __nv_bfloat16* pgh  = sym_addr<__nv_bfloat16>(g_grph);
    __nv_bfloat16* pgl  = sym_addr<__nv_bfloat16>(g_grpl);
    __nv_bfloat16* pt1h = sym_addr<__nv_bfloat16>(g_t1h);
    __nv_bfloat16* pt1l = sym_addr<__nv_bfloat16>(g_t1l);

    __nv_bfloat16* pwqkvh = sym_addr<__nv_bfloat16>(g_wqkvh);
    __nv_bfloat16* pwqkvl = sym_addr<__nv_bfloat16>(g_wqkvl);
    __nv_bfloat16* pwoh = sym_addr<__nv_bfloat16>(g_woh);
    __nv_bfloat16* pwol = sym_addr<__nv_bfloat16>(g_wol);
    __nv_bfloat16* pw12h = sym_addr<__nv_bfloat16>(g_w12h);
    __nv_bfloat16* pw12l = sym_addr<__nv_bfloat16>(g_w12l);
    __nv_bfloat16* pw3h = sym_addr<__nv_bfloat16>(g_w3h);
    __nv_bfloat16* pw3l = sym_addr<__nv_bfloat16>(g_w3l);

    dim3 tb(32, 8);
    // launches 0-4: rmsnorm + attention-path weight prepack
    rmsnorm_split_kernel<<<NTOK, 256>>>(x, n1s, phh, phl);                                  // 0
    tsplit_kernel<<<dim3(DD / 32, DD / 32, 1), tb>>>(wq, pwqkvh, pwqkvl, DD, DD, 0, 0);     // 1
    tsplit_kernel<<<dim3(256 / 32, DD / 32, 1), tb>>>(wk, pwqkvh + 1024 * DD, pwqkvl + 1024 * DD, DD, 256, 0, 0); // 2
    tsplit_kernel<<<dim3(256 / 32, DD / 32, 1), tb>>>(wv, pwqkvh + 1280 * DD, pwqkvl + 1280 * DD, DD, 256, 0, 0); // 3
    tsplit_kernel<<<dim3(DD / 32, DD / 32, 1), tb>>>(wo, pwoh, pwol, DD, DD, 0, 0);         // 4

    // launch 5 (ncu -s 5 profiles this): fused QKV GEMM, N=1536
    hmma_gemm<<<dim3(QKVN / 128, NTOK / 128, 1), 256, HM_SMEM>>>(
        phh, phl, pwqkvh, pwqkvl, pqkv, nullptr, QKVN, DD, 0, 0, 0);

    {
        long long tq = (long long)NTOK * HQ * 32;
        rope_kernel<<<(int)((tq + 255) / 256), 256>>>(pqkv, HQ, 0, tq);
        long long tk = (long long)NTOK * HKV * 32;
        rope_kernel<<<(int)((tk + 255) / 256), 256>>>(pqkv, HKV, 1024, tk);
    }
    attn_kernel<<<dim3(TT, HKV, BB), 256>>>(pqkv, path, patl);
    hmma_gemm<<<dim3(8, 16, 1), 256, HM_SMEM>>>(path, patl, pwoh, pwol, px1, x, 1024, HQ * VD, 0, 0, 0);

    // ---- MoE path ----
    tsplit_kernel<<<dim3(HID / 32, DD / 32, EE), tb>>>(w1, pw12h, pw12l, DD, HID,
        (long long)DD * HID, (long long)(2 * HID) * DD);
    tsplit_kernel<<<dim3(HID / 32, DD / 32, EE), tb>>>(w2, pw12h + (long long)HID * DD,
        pw12l + (long long)HID * DD, DD, HID,
        (long long)DD * HID, (long long)(2 * HID) * DD);
    tsplit_kernel<<<dim3(DD / 32, HID / 32, EE), tb>>>(w3, pw3h, pw3l, HID, DD,
        (long long)HID * DD, (long long)HID * DD);

    rmsnorm_kernel<<<NTOK, 256>>>(px1, n2s, ph2);
    router_kernel<<<NTOK, 128>>>(ph2, rw, rb, pgate, pexp);
    capacity_kernel<<<1, 256>>>(pexp, pslot, pkeep);
    cudaMemsetAsync(pgrp, 0, (size_t)EE * CAP * DD * sizeof(float));
    dispatch_kernel<<<NTOK * TOPK, 256>>>(ph2, pexp, pslot, pkeep, pgrp);
    split_kernel<<<2048, 256>>>(pgrp, pgh, pgl, (long long)EE * CAP * DD);

    // fused w1|w2 GEMM: N = 2*HID = 4096
    hmma_gemm<<<dim3((2 * HID) / 128, CAP / 128, EE), 256, HM_SMEM>>>(
        pgh, pgl, pw12h, pw12l, pt12, nullptr,
        2 * HID, DD, (long long)CAP * DD, (long long)(2 * HID) * DD, (long long)CAP * 2 * HID);
    gelu_split_kernel<<<2048, 256>>>(pt12, pt1h, pt1l, (long long)EE * CAP * HID);
    hmma_gemm<<<dim3(DD / 128, CAP / 128, EE), 256, HM_SMEM>>>(
        pt1h, pt1l, pw3h, pw3l, peout, nullptr,
        DD, HID, (long long)CAP * HID, (long long)HID * DD, (long long)CAP * DD);
    combine_kernel<<<NTOK, 256>>>(px1, ph2, peout, pgate, pexp, pslot, pkeep, out);
}

// round 9
// speedup vs baseline: 4.3834x; 1.3180x over previous
#include <cuda_runtime.h>
#include <cuda_bf16.h>
#include <cstdint>
#include <math.h>

// ---------------- problem constants ----------------
#define BB   2
#define TT   1024
#define DD   1024
#define NTOK (BB*TT)          // 2048
#define HQ   16
#define HKV  4
#define KD   64
#define VD   64
#define EE   8
#define TOPK 2
#define CAP  1024             // floor(2048*0.5)
#define HID  2048
#define EPS  1e-6f
#define QKVN 1536             // 1024 q + 256 k + 256 v

// ---------------- fp32 scratch ----------------
__device__ float g_qkv [NTOK*QKVN];      // fused q|k|v projection out
__device__ float g_x1  [NTOK*DD];
__device__ float g_h2  [NTOK*DD];
__device__ float g_gate[NTOK*TOPK];
__device__ int   g_expert[NTOK*TOPK];
__device__ int   g_slot  [NTOK*TOPK];
__device__ int   g_keep  [NTOK*TOPK];
__device__ int   g_cnt   [EE];           // valid rows per expert
__device__ float g_grouped[EE*CAP*DD];
__device__ float g_eout[EE*CAP*DD];

// ---------------- bf16 split activations (hi/lo) ----------------
__device__ __nv_bfloat16 g_hh [NTOK*DD],     g_hl [NTOK*DD];      // rmsnorm1 out
__device__ __nv_bfloat16 g_ath[NTOK*HQ*VD],  g_atl[NTOK*HQ*VD];   // attn out
__device__ __nv_bfloat16 g_grph[EE*CAP*DD],  g_grpl[EE*CAP*DD];   // dispatched
__device__ __nv_bfloat16 g_t1h[EE*CAP*HID],  g_t1l[EE*CAP*HID];   // gelu out

// ---------------- bf16 split transposed weights [N][K] ----------------
__device__ __nv_bfloat16 g_wqkvh[QKVN*DD],  g_wqkvl[QKVN*DD];     // wq|wk|wv
__device__ __nv_bfloat16 g_woh[DD*DD],      g_wol[DD*DD];
__device__ __nv_bfloat16 g_w12h[EE*2*HID*DD], g_w12l[EE*2*HID*DD]; // w1|w2 row-interleaved
__device__ __nv_bfloat16 g_w3h[EE*DD*HID],  g_w3l[EE*DD*HID];

// ================= PTX helpers =================
__device__ __forceinline__ uint32_t smem_u32(const void* p) {
    uint32_t a;
    asm("{ .reg .u64 t; cvta.to.shared.u64 t, %1; cvt.u32.u64 %0, t; }" : "=r"(a) : "l"(p));
    return a;
}
__device__ __forceinline__ void cp16(uint32_t dst, const void* src) {
    asm volatile("cp.async.ca.shared.global [%0], [%1], 16;" :: "r"(dst), "l"(src) : "memory");
}
#define CP_COMMIT() asm volatile("cp.async.commit_group;" ::: "memory")
#define CP_WAIT(n)  asm volatile("cp.async.wait_group %0;" :: "n"(n) : "memory")

#define LDSM4(r0, r1, r2, r3, addr) \
    asm volatile("ldmatrix.sync.aligned.m8n8.x4.shared.b16 {%0,%1,%2,%3}, [%4];" \
        : "=r"(r0), "=r"(r1), "=r"(r2), "=r"(r3) : "r"(addr))

#define MMA_BF16(d, a, b) \
    asm volatile("mma.sync.aligned.m16n8k16.row.col.f32.bf16.bf16.f32 " \
        "{%0,%1,%2,%3}, {%4,%5,%6,%7}, {%8,%9}, {%0,%1,%2,%3};" \
        : "+f"((d)[0]), "+f"((d)[1]), "+f"((d)[2]), "+f"((d)[3]) \
        : "r"((a)[0]), "r"((a)[1]), "r"((a)[2]), "r"((a)[3]), \
          "r"((b)[0]), "r"((b)[1]))

__device__ __forceinline__ void split1(float v, __nv_bfloat16& h, __nv_bfloat16& l) {
    h = __float2bfloat16(v);
    l = __float2bfloat16(v - __bfloat162float(h));
}
__device__ __forceinline__ float gelu1(float x) {
    float inner = 0.7978845608028654f * (x + 0.044715f * x * x * x);
    return 0.5f * x * (1.0f + tanhf(inner));
}

// ================= split-bf16 HMMA GEMM =================
// C[M,N] (+Res) = A[M,K] * Bt[N,K]^T, A/B given as (hi,lo) bf16 pairs.
// CTA tile 128x128, BK=32 double-buffered cp.async, 8 warps of 64x32.
// 3 MMA terms (hh, hl, lh) accumulate into the same fp32 registers.
// cnt: optional per-batch valid-row count (early-exit tiles beyond it).
// geluMode: output = split-bf16 gelu(even_col * odd_col), hidden width N/2.
#define STAGE_BYTES 32768

__device__ __forceinline__ void hmma_compute_stage(
    uint32_t sb, int lane, int m0w, int n0w, float acc[4][4][4])
{
#pragma unroll
    for (int s = 0; s < 2; s++) {
        uint32_t ah[4][4], al[4][4], bh[4][2], bl[4][2];
#pragma unroll
        for (int mi = 0; mi < 4; mi++) {
            int row = m0w + mi * 16 + (lane & 15);
            int j = s * 2 + (lane >> 4);
            uint32_t ad = sb + row * 64 + ((j ^ (row & 3)) << 4);
            LDSM4(ah[mi][0], ah[mi][1], ah[mi][2], ah[mi][3], ad);
            LDSM4(al[mi][0], al[mi][1], al[mi][2], al[mi][3], ad + 8192);
        }
#pragma unroll
        for (int np = 0; np < 2; np++) {
            int q = lane >> 3;
            int row = n0w + np * 16 + ((q >> 1) << 3) + (lane & 7);
            int j = s * 2 + (q & 1);
            uint32_t bd = sb + 16384 + row * 64 + ((j ^ (row & 3)) << 4);
            LDSM4(bh[2 * np][0], bh[2 * np][1], bh[2 * np + 1][0], bh[2 * np + 1][1], bd);
            LDSM4(bl[2 * np][0], bl[2 * np][1], bl[2 * np + 1][0], bl[2 * np + 1][1], bd + 8192);
        }
#pragma unroll
        for (int mi = 0; mi < 4; mi++) {
#pragma unroll
            for (int ni = 0; ni < 4; ni++) {
                MMA_BF16(acc[mi][ni], ah[mi], bh[ni]);
                MMA_BF16(acc[mi][ni], ah[mi], bl[ni]);
                MMA_BF16(acc[mi][ni], al[mi], bh[ni]);
            }
        }
    }
}

__global__ __launch_bounds__(256, 1)
void hmma_gemm(const __nv_bfloat16* __restrict__ Ah, const __nv_bfloat16* __restrict__ Al,
               const __nv_bfloat16* __restrict__ Bh, const __nv_bfloat16* __restrict__ Bl,
               float* __restrict__ C, const float* __restrict__ Res,
               int N, int K,
               long long sA, long long sB, long long sC,
               const int* __restrict__ cnt, int geluMode,
               __nv_bfloat16* __restrict__ Gh, __nv_bfloat16* __restrict__ Gl)
{
    extern __shared__ char sm[];
    const int rowBase = blockIdx.y * 128;
    if (cnt && rowBase >= cnt[blockIdx.z]) return;   // zero rows -> outputs unread

    Ah += (long long)blockIdx.z * sA; Al += (long long)blockIdx.z * sA;
    Bh += (long long)blockIdx.z * sB; Bl += (long long)blockIdx.z * sB;

    const int tid = threadIdx.x, wid = tid >> 5, lane = tid & 31;
    const int colBase = blockIdx.x * 128;
    const int m0w = (wid >> 2) * 64, n0w = (wid & 3) * 32;
    uint32_t smb = smem_u32(sm);

    float acc[4][4][4];
#pragma unroll
    for (int mi = 0; mi < 4; mi++)
#pragma unroll
        for (int ni = 0; ni < 4; ni++)
#pragma unroll
            for (int r = 0; r < 4; r++) acc[mi][ni][r] = 0.f;

    const int KC = K >> 5;

    {
        uint32_t sb = smb;
#pragma unroll
        for (int p = 0; p < 2; p++) {
            int idx = tid + p * 256;
            int r = idx >> 2, j = idx & 3;
            uint32_t so = r * 64 + ((j ^ (r & 3)) << 4);
            long long ga = (long long)(rowBase + r) * K + j * 8;
            long long gb = (long long)(colBase + r) * K + j * 8;
            cp16(sb + so,         Ah + ga);
            cp16(sb + 8192 + so,  Al + ga);
            cp16(sb + 16384 + so, Bh + gb);
            cp16(sb + 24576 + so, Bl + gb);
        }
        CP_COMMIT();
    }

    for (int c = 0; c < KC; c++) {
        if (c + 1 < KC) {
            uint32_t sb = smb + ((c + 1) & 1) * STAGE_BYTES;
            long long k0 = (long long)(c + 1) * 32;
#pragma unroll
            for (int p = 0; p < 2; p++) {
                int idx = tid + p * 256;
                int r = idx >> 2, j = idx & 3;
                uint32_t so = r * 64 + ((j ^ (r & 3)) << 4);
                long long ga = (long long)(rowBase + r) * K + k0 + j * 8;
                long long gb = (long long)(colBase + r) * K + k0 + j * 8;
                cp16(sb + so,         Ah + ga);
                cp16(sb + 8192 + so,  Al + ga);
                cp16(sb + 16384 + so, Bh + gb);
                cp16(sb + 24576 + so, Bl + gb);
            }
            CP_COMMIT();
            CP_WAIT(1);
        } else {
            CP_WAIT(0);
        }
        __syncthreads();
        hmma_compute_stage(smb + (c & 1) * STAGE_BYTES, lane, m0w, n0w, acc);
        __syncthreads();
    }

    if (geluMode) {
        // even col = w1@x (a), odd col = w2@x (b); out hidden col = col/2
        const int NH = N >> 1;
        Gh += (long long)blockIdx.z * sC;
        Gl += (long long)blockIdx.z * sC;
#pragma unroll
        for (int mi = 0; mi < 4; mi++) {
#pragma unroll
            for (int ni = 0; ni < 4; ni++) {
                int row = rowBase + m0w + mi * 16 + (lane >> 2);
                int hcol = (colBase + n0w + ni * 8 + (lane & 3) * 2) >> 1;
                float g0 = gelu1(acc[mi][ni][0] * acc[mi][ni][1]);
                float g1 = gelu1(acc[mi][ni][2] * acc[mi][ni][3]);
                __nv_bfloat16 h, l;
                split1(g0, h, l);
                Gh[(long long)row * NH + hcol] = h;
                Gl[(long long)row * NH + hcol] = l;
                split1(g1, h, l);
                Gh[(long long)(row + 8) * NH + hcol] = h;
                Gl[(long long)(row + 8) * NH + hcol] = l;
            }
        }
        return;
    }

    C += (long long)blockIdx.z * sC;
#pragma unroll
    for (int mi = 0; mi < 4; mi++) {
#pragma unroll
        for (int ni = 0; ni < 4; ni++) {
            int row = rowBase + m0w + mi * 16 + (lane >> 2);
            int col = colBase + n0w + ni * 8 + (lane & 3) * 2;
            float2 v0 = make_float2(acc[mi][ni][0], acc[mi][ni][1]);
            float2 v1 = make_float2(acc[mi][ni][2], acc[mi][ni][3]);
            long long o0 = (long long)row * N + col;
            long long o1 = (long long)(row + 8) * N + col;
            if (Res) {
                float2 r0 = *(const float2*)&Res[o0];
                float2 r1 = *(const float2*)&Res[o1];
                v0.x += r0.x; v0.y += r0.y;
                v1.x += r1.x; v1.y += r1.y;
            }
            *(float2*)&C[o0] = v0;
            *(float2*)&C[o1] = v1;
        }
    }
}

// ================= prepack kernels =================
// transpose + split: W [K][N] (batched) -> Th/Tl rows (n*rowMul + rowAdd), K cols
__global__ void tsplit_kernel(const float* __restrict__ W,
                              __nv_bfloat16* __restrict__ Th, __nv_bfloat16* __restrict__ Tl,
                              int K, int N, long long sW, long long sT,
                              int rowMul, int rowAdd) {
    __shared__ float tile[32][33];
    W  += (long long)blockIdx.z * sW;
    Th += (long long)blockIdx.z * sT;
    Tl += (long long)blockIdx.z * sT;
    int n0 = blockIdx.x * 32, k0 = blockIdx.y * 32;
    int tx = threadIdx.x, ty = threadIdx.y;
    for (int i = ty; i < 32; i += 8)
        tile[i][tx] = W[(long long)(k0 + i) * N + n0 + tx];
    __syncthreads();
    for (int i = ty; i < 32; i += 8) {
        float v = tile[tx][i];  // W[k0+tx][n0+i]
        __nv_bfloat16 h, l; split1(v, h, l);
        long long o = ((long long)(n0 + i) * rowMul + rowAdd) * K + k0 + tx;
        Th[o] = h; Tl[o] = l;
    }
}

__global__ void split_kernel(const float* __restrict__ X,
                             __nv_bfloat16* __restrict__ H, __nv_bfloat16* __restrict__ L,
                             long long n) {
    long long i = (long long)blockIdx.x * blockDim.x + threadIdx.x;
    long long stride = (long long)gridDim.x * blockDim.x;
    for (; i < n; i += stride) {
        __nv_bfloat16 h, l; split1(X[i], h, l);
        H[i] = h; L[i] = l;
    }
}

// ================= rmsnorm =================
__global__ void rmsnorm_kernel(const float* __restrict__ x, const float* __restrict__ scale,
                               float* __restrict__ out) {
    int n = blockIdx.x, tid = threadIdx.x;
    __shared__ float red[256];
    const float* xr = x + (long long)n * DD;
    float ss = 0.f;
    for (int d = tid; d < DD; d += 256) { float v = xr[d]; ss += v * v; }
    red[tid] = ss; __syncthreads();
    for (int s = 128; s > 0; s >>= 1) { if (tid < s) red[tid] += red[tid + s]; __syncthreads(); }
    float inv = rsqrtf(red[0] / (float)DD + EPS);
    float* o = out + (long long)n * DD;
    for (int d = tid; d < DD; d += 256) o[d] = xr[d] * inv * scale[d];
}

__global__ void rmsnorm_split_kernel(const float* __restrict__ x, const float* __restrict__ scale,
                                     __nv_bfloat16* __restrict__ oh, __nv_bfloat16* __restrict__ ol) {
    int n = blockIdx.x, tid = threadIdx.x;
    __shared__ float red[256];
    const float* xr = x + (long long)n * DD;
    float ss = 0.f;
    for (int d = tid; d < DD; d += 256) { float v = xr[d]; ss += v * v; }
    red[tid] = ss; __syncthreads();
    for (int s = 128; s > 0; s >>= 1) { if (tid < s) red[tid] += red[tid + s]; __syncthreads(); }
    float inv = rsqrtf(red[0] / (float)DD + EPS);
    for (int d = tid; d < DD; d += 256) {
        float o = xr[d] * inv * scale[d];
        __nv_bfloat16 h, l; split1(o, h, l);
        oh[(long long)n * DD + d] = h;
        ol[(long long)n * DD + d] = l;
    }
}

// ================= rope (in-place on fused qkv buffer) =================
__global__ void rope_kernel(float* __restrict__ qkv, int H, int colOff, long long total) {
    long long i = (long long)blockIdx.x * blockDim.x + threadIdx.x;
    if (i >= total) return;
    int half = (int)(i & 31);
    long long nh = i >> 5;
    int h = (int)(nh % H);
    long long tok = nh / H;
    int t = (int)(tok % TT);
    float theta = __powf(10000.0f, -(float)(2 * half) / 64.0f);
    float ang = (float)t * theta;
    float s = sinf(ang), c = cosf(ang);
    float* p = qkv + tok * QKVN + colOff + h * 64;
    float x1 = p[half], x2 = p[half + 32];
    p[half]      = x1 * c - x2 * s;
    p[half + 32] = x2 * c + x1 * s;
}

// ================= attention =================
// One block per (t, kv_head, batch); processes all G=4 query heads sharing k/v.
__global__ __launch_bounds__(256)
void attn_kernel(const float* __restrict__ qkv,
                 __nv_bfloat16* __restrict__ oh, __nv_bfloat16* __restrict__ ol) {
    int t = blockIdx.x, kvh = blockIdx.y, b = blockIdx.z;
    int tid = threadIdx.x, wid = tid >> 5, lane = tid & 31;
    __shared__ float qs[4][64];
    __shared__ float sc[4][TT];
    __shared__ float wacc[8][4][64];
    __shared__ float red[8][4];
    __shared__ float hmax[4], hinv[4];

    const float* base = qkv + (long long)(b * TT) * QKVN;
    {
        int g = tid >> 6, d = tid & 63;
        qs[g][d] = base[(long long)t * QKVN + (kvh * 4 + g) * 64 + d];
    }
    __syncthreads();

    int L = t + 1;
    const float* kbase = base + 1024 + kvh * 64;
    const float* vbase = base + 1280 + kvh * 64;

    float m[4] = {-1e30f, -1e30f, -1e30f, -1e30f};
    for (int s = wid; s < L; s += 8) {
        const float* kr = kbase + (long long)s * QKVN;
        float k0 = kr[lane], k1 = kr[lane + 32];
#pragma unroll
        for (int g = 0; g < 4; g++) {
            float d = qs[g][lane] * k0 + qs[g][lane + 32] * k1;
            d += __shfl_down_sync(0xffffffffu, d, 16);
            d += __shfl_down_sync(0xffffffffu, d, 8);
            d += __shfl_down_sync(0xffffffffu, d, 4);
            d += __shfl_down_sync(0xffffffffu, d, 2);
            d += __shfl_down_sync(0xffffffffu, d, 1);
            if (lane == 0) {
                d *= 0.125f;
                sc[g][s] = d;
                m[g] = fmaxf(m[g], d);
            }
        }
    }
    if (lane == 0) {
#pragma unroll
        for (int g = 0; g < 4; g++) red[wid][g] = m[g];
    }
    __syncthreads();
    if (tid < 4) {
        float mm = -1e30f;
        for (int w = 0; w < 8; w++) mm = fmaxf(mm, red[w][tid]);
        hmax[tid] = mm;
    }
    __syncthreads();

    float s0 = 0, s1 = 0, s2 = 0, s3 = 0;
    float hm0 = hmax[0], hm1 = hmax[1], hm2 = hmax[2], hm3 = hmax[3];
    for (int s = tid; s < L; s += 256) {
        float e;
        e = expf(sc[0][s] - hm0); sc[0][s] = e; s0 += e;
        e = expf(sc[1][s] - hm1); sc[1][s] = e; s1 += e;
        e = expf(sc[2][s] - hm2); sc[2][s] = e; s2 += e;
        e = expf(sc[3][s] - hm3); sc[3][s] = e; s3 += e;
    }
#pragma unroll
    for (int off = 16; off > 0; off >>= 1) {
        s0 += __shfl_down_sync(0xffffffffu, s0, off);
        s1 += __shfl_down_sync(0xffffffffu, s1, off);
        s2 += __shfl_down_sync(0xffffffffu, s2, off);
        s3 += __shfl_down_sync(0xffffffffu, s3, off);
    }
    __syncthreads();
    if (lane == 0) { red[wid][0] = s0; red[wid][1] = s1; red[wid][2] = s2; red[wid][3] = s3; }
    __syncthreads();
    if (tid < 4) {
        float ssum = 0;
        for (int w = 0; w < 8; w++) ssum += red[w][tid];
        hinv[tid] = 1.0f / ssum;
    }
    __syncthreads();

    float a00 = 0, a01 = 0, a10 = 0, a11 = 0, a20 = 0, a21 = 0, a30 = 0, a31 = 0;
    for (int s = wid; s < L; s += 8) {
        const float* vr = vbase + (long long)s * QKVN;
        float v0 = vr[lane], v1 = vr[lane + 32];
        float w0 = sc[0][s], w1 = sc[1][s], w2 = sc[2][s], w3 = sc[3][s];
        a00 += w0 * v0; a01 += w0 * v1;
        a10 += w1 * v0; a11 += w1 * v1;
        a20 += w2 * v0; a21 += w2 * v1;
        a30 += w3 * v0; a31 += w3 * v1;
    }
    wacc[wid][0][lane] = a00; wacc[wid][0][lane + 32] = a01;
    wacc[wid][1][lane] = a10; wacc[wid][1][lane + 32] = a11;
    wacc[wid][2][lane] = a20; wacc[wid][2][lane + 32] = a21;
    wacc[wid][3][lane] = a30; wacc[wid][3][lane + 32] = a31;
    __syncthreads();
    {
        int g = tid >> 6, d = tid & 63;
        float acc = 0;
#pragma unroll
        for (int w = 0; w < 8; w++) acc += wacc[w][g][d];
        acc *= hinv[g];
        long long idx = ((long long)(b * TT + t) * HQ + kvh * 4 + g) * 64 + d;
        __nv_bfloat16 h, l; split1(acc, h, l);
        oh[idx] = h; ol[idx] = l;
    }
}

// ================= router / capacity / dispatch / combine =================
__global__ void router_kernel(const float* __restrict__ h2, const float* __restrict__ rw,
                              const float* __restrict__ rb,
                              float* __restrict__ gate, int* __restrict__ expert) {
    int n = blockIdx.x, tid = threadIdx.x;
    __shared__ float part[128][8];
    float acc[8];
#pragma unroll
    for (int e = 0; e < 8; e++) acc[e] = 0.f;
    const float* xr = h2 + (long long)n * DD;
    for (int d = tid; d < DD; d += 128) {
        float xv = xr[d];
#pragma unroll
        for (int e = 0; e < 8; e++) acc[e] += xv * rw[d * 8 + e];
    }
#pragma unroll
    for (int e = 0; e < 8; e++) part[tid][e] = acc[e];
    __syncthreads();
    if (tid < 8) {
        float s = rb[tid];
        for (int i = 0; i < 128; i++) s += part[i][tid];
        part[0][tid] = s;
    }
    __syncthreads();
    if (tid == 0) {
        float lg[8];
#pragma unroll
        for (int e = 0; e < 8; e++) lg[e] = part[0][e];
        int i0 = 0;
        for (int e = 1; e < 8; e++) if (lg[e] > lg[i0]) i0 = e;
        int i1 = -1;
        for (int e = 0; e < 8; e++) {
            if (e == i0) continue;
            if (i1 < 0 || lg[e] > lg[i1]) i1 = e;
        }
        float a = lg[i0], bq = lg[i1];
        float ea = 1.0f, eb = expf(bq - a);
        float s = ea + eb;
        gate[n * 2] = ea / s; gate[n * 2 + 1] = eb / s;
        expert[n * 2] = i0;   expert[n * 2 + 1] = i1;
    }
}

__global__ void capacity_kernel(const int* __restrict__ expert,
                                int* __restrict__ slot, int* __restrict__ keep,
                                int* __restrict__ cnt) {
    int w = threadIdx.x >> 5;
    int lane = threadIdx.x & 31;
    if (w >= EE) return;
    int c0 = 0, c1 = 0;
    unsigned le = 0xffffffffu >> (31 - lane);
    for (int base = 0; base < NTOK; base += 32) {
        int n = base + lane;
        int e0 = expert[n * 2], e1 = expert[n * 2 + 1];
        unsigned m0 = __ballot_sync(0xffffffffu, e0 == w);
        unsigned m1 = __ballot_sync(0xffffffffu, e1 == w);
        int inc0 = __popc(m0 & le);
        int inc1 = __popc(m1 & le);
        if (e0 == w) {
            int p0 = c0 + inc0;
            keep[n * 2] = (p0 < CAP) ? 1 : 0;
            slot[n * 2] = p0;
        }
        if (e1 == w) {
            int p1 = c0 + inc0 + c1 + inc1;
            keep[n * 2 + 1] = (p1 < CAP) ? 1 : 0;
            slot[n * 2 + 1] = p1;
        }
        c0 += __popc(m0); c1 += __popc(m1);
    }
    if (lane == 0) {
        int tot = c0 + c1 + 1;             // max used slot index + 1 (slots are 1-based)
        cnt[w] = tot < CAP ? tot : CAP;
    }
}

__global__ void dispatch_kernel(const float* __restrict__ h2, const int* __restrict__ expert,
                                const int* __restrict__ slot, const int* __restrict__ keep,
                                float* __restrict__ grouped) {
    int idx = blockIdx.x;
    if (!keep[idx]) return;
    int n = idx >> 1;
    int e = expert[idx], p = slot[idx];
    float* dst = grouped + ((long long)e * CAP + p) * DD;
    const float* src = h2 + (long long)n * DD;
    for (int d = threadIdx.x; d < DD; d += blockDim.x) atomicAdd(&dst[d], src[d]);
}

__global__ void combine_kernel(const float* __restrict__ x1, const float* __restrict__ h2,
                               const float* __restrict__ eout, const float* __restrict__ gate,
                               const int* __restrict__ expert, const int* __restrict__ slot,
                               const int* __restrict__ keep, float* __restrict__ out) {
    int n = blockIdx.x, tid = threadIdx.x;
    float g0 = gate[n * 2], g1 = gate[n * 2 + 1];
    const float* s0 = keep[n * 2]
        ? eout + ((long long)expert[n * 2] * CAP + slot[n * 2]) * DD
        : h2 + (long long)n * DD;
    const float* s1 = keep[n * 2 + 1]
        ? eout + ((long long)expert[n * 2 + 1] * CAP + slot[n * 2 + 1]) * DD
        : h2 + (long long)n * DD;
    const float* xr = x1 + (long long)n * DD;
    float* o = out + (long long)n * DD;
    for (int d = tid; d < DD; d += 256)
        o[d] = xr[d] + g0 * s0[d] + g1 * s1[d];
}

// ================= host launch =================
template <typename T>
static T* sym_addr(const void* sym) {
    void* p = nullptr;
    cudaGetSymbolAddress(&p, sym);
    return (T*)p;
}

#define HM_SMEM (2 * STAGE_BYTES)

extern "C" void kernel_launch(void* const* d_in, const int* in_sizes, int n_in,
                              void* d_out, int out_size) {
    const float* x   = (const float*)d_in[0];
    const float* wq  = (const float*)d_in[1];
    const float* wk  = (const float*)d_in[2];
    const float* wv  = (const float*)d_in[3];
    const float* wo  = (const float*)d_in[4];
    const float* rw  = (const float*)d_in[5];
    const float* rb  = (const float*)d_in[6];
    const float* w1  = (const float*)d_in[7];
    const float* w2  = (const float*)d_in[8];
    const float* w3  = (const float*)d_in[9];
    const float* n1s = (const float*)d_in[10];
    const float* n2s = (const float*)d_in[11];
    float* out = (float*)d_out;

    cudaFuncSetAttribute(hmma_gemm, cudaFuncAttributeMaxDynamicSharedMemorySize, HM_SMEM);

    float* pqkv  = sym_addr<float>(g_qkv);
    float* px1   = sym_addr<float>(g_x1);
    float* ph2   = sym_addr<float>(g_h2);
    float* pgate = sym_addr<float>(g_gate);
    int*   pexp  = sym_addr<int>(g_expert);
    int*   pslot = sym_addr<int>(g_slot);
    int*   pkeep = sym_addr<int>(g_keep);
    int*   pcnt  = sym_addr<int>(g_cnt);
    float* pgrp  = sym_addr<float>(g_grouped);
    float* peout = sym_addr<float>(g_eout);

    __nv_bfloat16* phh  = sym_addr<__nv_bfloat16>(g_hh);
    __nv_bfloat16* phl  = sym_addr<__nv_bfloat16>(g_hl);
    __nv_bfloat16* path = sym_addr<__nv_bfloat16>(g_ath);
    __nv_bfloat16* patl = sym_addr<__nv_bfloat16>(g_atl);
    __nv_bfloat16* pgh  = sym_addr<__nv_bfloat16>(g_grph);
    __nv_bfloat16* pgl  = sym_addr<__nv_bfloat16>(g_grpl);
    __nv_bfloat16* pt1h = sym_addr<__nv_bfloat16>(g_t1h);
    __nv_bfloat16* pt1l = sym_addr<__nv_bfloat16>(g_t1l);

    __nv_bfloat16* pwqkvh = sym_addr<__nv_bfloat16>(g_wqkvh);
    __nv_bfloat16* pwqkvl = sym_addr<__nv_bfloat16>(g_wqkvl);
    __nv_bfloat16* pwoh = sym_addr<__nv_bfloat16>(g_woh);
    __nv_bfloat16* pwol = sym_addr<__nv_bfloat16>(g_wol);
    __nv_bfloat16* pw12h = sym_addr<__nv_bfloat16>(g_w12h);
    __nv_bfloat16* pw12l = sym_addr<__nv_bfloat16>(g_w12l);
    __nv_bfloat16* pw3h = sym_addr<__nv_bfloat16>(g_w3h);
    __nv_bfloat16* pw3l = sym_addr<__nv_bfloat16>(g_w3l);

    dim3 tb(32, 8);
    // ---- attention-path prepack ----
    rmsnorm_split_kernel<<<NTOK, 256>>>(x, n1s, phh, phl);
    tsplit_kernel<<<dim3(DD / 32, DD / 32, 1), tb>>>(wq, pwqkvh, pwqkvl, DD, DD, 0, 0, 1, 0);
    tsplit_kernel<<<dim3(256 / 32, DD / 32, 1), tb>>>(wk, pwqkvh + 1024 * DD, pwqkvl + 1024 * DD, DD, 256, 0, 0, 1, 0);
    tsplit_kernel<<<dim3(256 / 32, DD / 32, 1), tb>>>(wv, pwqkvh + 1280 * DD, pwqkvl + 1280 * DD, DD, 256, 0, 0, 1, 0);
    tsplit_kernel<<<dim3(DD / 32, DD / 32, 1), tb>>>(wo, pwoh, pwol, DD, DD, 0, 0, 1, 0);

    // fused QKV GEMM, N=1536
    hmma_gemm<<<dim3(QKVN / 128, NTOK / 128, 1), 256, HM_SMEM>>>(
        phh, phl, pwqkvh, pwqkvl, pqkv, nullptr, QKVN, DD, 0, 0, 0,
        nullptr, 0, nullptr, nullptr);

    {
        long long tq = (long long)NTOK * HQ * 32;
        rope_kernel<<<(int)((tq + 255) / 256), 256>>>(pqkv, HQ, 0, tq);
        long long tk = (long long)NTOK * HKV * 32;
        rope_kernel<<<(int)((tk + 255) / 256), 256>>>(pqkv, HKV, 1024, tk);
    }
    attn_kernel<<<dim3(TT, HKV, BB), 256>>>(pqkv, path, patl);
    hmma_gemm<<<dim3(8, 16, 1), 256, HM_SMEM>>>(path, patl, pwoh, pwol, px1, x, 1024, HQ * VD, 0, 0, 0,
        nullptr, 0, nullptr, nullptr);

    // ---- MoE weight prepack (w1/w2 row-interleaved for fused gelu) ----
    tsplit_kernel<<<dim3(HID / 32, DD / 32, EE), tb>>>(w1, pw12h, pw12l, DD, HID,
        (long long)DD * HID, (long long)(2 * HID) * DD, 2, 0);
    tsplit_kernel<<<dim3(HID / 32, DD / 32, EE), tb>>>(w2, pw12h, pw12l, DD, HID,
        (long long)DD * HID, (long long)(2 * HID) * DD, 2, 1);
    tsplit_kernel<<<dim3(DD / 32, HID / 32, EE), tb>>>(w3, pw3h, pw3l, HID, DD,
        (long long)HID * DD, (long long)HID * DD, 1, 0);

    rmsnorm_kernel<<<NTOK, 256>>>(px1, n2s, ph2);
    router_kernel<<<NTOK, 128>>>(ph2, rw, rb, pgate, pexp);
    capacity_kernel<<<1, 256>>>(pexp, pslot, pkeep, pcnt);
    cudaMemsetAsync(pgrp, 0, (size_t)EE * CAP * DD * sizeof(float));
    dispatch_kernel<<<NTOK * TOPK, 256>>>(ph2, pexp, pslot, pkeep, pgrp);
    split_kernel<<<2048, 256>>>(pgrp, pgh, pgl, (long long)EE * CAP * DD);

    // fused w1|w2 GEMM with gelu epilogue -> split-bf16 t1 (zero-row tiles skipped)
    hmma_gemm<<<dim3((2 * HID) / 128, CAP / 128, EE), 256, HM_SMEM>>>(
        pgh, pgl, pw12h, pw12l, nullptr, nullptr,
        2 * HID, DD, (long long)CAP * DD, (long long)(2 * HID) * DD, (long long)CAP * HID,
        pcnt, 1, pt1h, pt1l);
    // w3 GEMM (zero-row tiles skipped)
    hmma_gemm<<<dim3(DD / 128, CAP / 128, EE), 256, HM_SMEM>>>(
        pt1h, pt1l, pw3h, pw3l, peout, nullptr,
        DD, HID, (long long)CAP * HID, (long long)HID * DD, (long long)CAP * DD,
        pcnt, 0, nullptr, nullptr);
    combine_kernel<<<NTOK, 256>>>(px1, ph2, peout, pgate, pexp, pslot, pkeep, out);
}

// round 11
// speedup vs baseline: 6.5667x; 1.4981x over previous
#include <cuda_runtime.h>
#include <cuda_bf16.h>
#include <cstdint>
#include <math.h>

// ---------------- problem constants ----------------
#define BB   2
#define TT   1024
#define DD   1024
#define NTOK (BB*TT)          // 2048
#define HQ   16
#define HKV  4
#define KD   64
#define VD   64
#define EE   8
#define TOPK 2
#define CAP  1024             // floor(2048*0.5)
#define HID  2048
#define EPS  1e-6f
#define QKVN 1536             // 1024 q + 256 k + 256 v

// ---------------- fp32 scratch ----------------
__device__ float g_qkv [NTOK*QKVN];      // fused q|k|v projection out
__device__ float g_x1  [NTOK*DD];
__device__ float g_h2  [NTOK*DD];
__device__ float g_gate[NTOK*TOPK];
__device__ int   g_expert[NTOK*TOPK];
__device__ int   g_slot  [NTOK*TOPK];
__device__ int   g_keep  [NTOK*TOPK];
__device__ int   g_cnt   [EE];           // valid rows per expert
__device__ float g_grouped[EE*CAP*DD];
__device__ float g_eout[EE*CAP*DD];

// ---------------- bf16 split activations (hi/lo) ----------------
__device__ __nv_bfloat16 g_hh [NTOK*DD],     g_hl [NTOK*DD];      // rmsnorm1 out
__device__ __nv_bfloat16 g_ath[NTOK*HQ*VD],  g_atl[NTOK*HQ*VD];   // attn out
__device__ __nv_bfloat16 g_grph[EE*CAP*DD],  g_grpl[EE*CAP*DD];   // dispatched
__device__ __nv_bfloat16 g_t1h[EE*CAP*HID],  g_t1l[EE*CAP*HID];   // gelu out

// packed attention inputs (rope applied to q,k; v transposed [d][tok])
__device__ __nv_bfloat16 g_qph[BB*HQ*TT*64],  g_qpl[BB*HQ*TT*64];
__device__ __nv_bfloat16 g_kph[BB*HKV*TT*64], g_kpl[BB*HKV*TT*64];
__device__ __nv_bfloat16 g_vph[BB*HKV*64*TT], g_vpl[BB*HKV*64*TT];

// ---------------- bf16 split transposed weights [N][K] ----------------
__device__ __nv_bfloat16 g_wqkvh[QKVN*DD],  g_wqkvl[QKVN*DD];     // wq|wk|wv
__device__ __nv_bfloat16 g_woh[DD*DD],      g_wol[DD*DD];
__device__ __nv_bfloat16 g_w12h[EE*2*HID*DD], g_w12l[EE*2*HID*DD]; // w1|w2 row-interleaved
__device__ __nv_bfloat16 g_w3h[EE*DD*HID],  g_w3l[EE*DD*HID];

// ================= PTX helpers =================
__device__ __forceinline__ uint32_t smem_u32(const void* p) {
    uint32_t a;
    asm("{ .reg .u64 t; cvta.to.shared.u64 t, %1; cvt.u32.u64 %0, t; }" : "=r"(a) : "l"(p));
    return a;
}
__device__ __forceinline__ void cp16(uint32_t dst, const void* src) {
    asm volatile("cp.async.ca.shared.global [%0], [%1], 16;" :: "r"(dst), "l"(src) : "memory");
}
#define CP_COMMIT() asm volatile("cp.async.commit_group;" ::: "memory")
#define CP_WAIT(n)  asm volatile("cp.async.wait_group %0;" :: "n"(n) : "memory")

#define LDSM4(r0, r1, r2, r3, addr) \
    asm volatile("ldmatrix.sync.aligned.m8n8.x4.shared.b16 {%0,%1,%2,%3}, [%4];" \
        : "=r"(r0), "=r"(r1), "=r"(r2), "=r"(r3) : "r"(addr))

#define MMA_BF16(d, a, b) \
    asm volatile("mma.sync.aligned.m16n8k16.row.col.f32.bf16.bf16.f32 " \
        "{%0,%1,%2,%3}, {%4,%5,%6,%7}, {%8,%9}, {%0,%1,%2,%3};" \
        : "+f"((d)[0]), "+f"((d)[1]), "+f"((d)[2]), "+f"((d)[3]) \
        : "r"((a)[0]), "r"((a)[1]), "r"((a)[2]), "r"((a)[3]), \
          "r"((b)[0]), "r"((b)[1]))

__device__ __forceinline__ void split1(float v, __nv_bfloat16& h, __nv_bfloat16& l) {
    h = __float2bfloat16(v);
    l = __float2bfloat16(v - __bfloat162float(h));
}
__device__ __forceinline__ float gelu1(float x) {
    float inner = 0.7978845608028654f * (x + 0.044715f * x * x * x);
    return 0.5f * x * (1.0f + tanhf(inner));
}
// pack two fp32 -> bf16x2 (lo = first element, hi = second)
__device__ __forceinline__ uint32_t packbf(float lo, float hi) {
    uint32_t r;
    asm("cvt.rn.bf16x2.f32 %0, %1, %2;" : "=r"(r) : "f"(hi), "f"(lo));
    return r;
}
__device__ __forceinline__ void split2pack(float x0, float x1, uint32_t& h, uint32_t& l) {
    __nv_bfloat16 h0 = __float2bfloat16(x0), h1 = __float2bfloat16(x1);
    h = ((uint32_t)__bfloat16_as_ushort(h1) << 16) | __bfloat16_as_ushort(h0);
    l = packbf(x0 - __bfloat162float(h0), x1 - __bfloat162float(h1));
}

// ================= split-bf16 HMMA GEMM =================
#define STAGE_BYTES 32768

__device__ __forceinline__ void hmma_compute_stage(
    uint32_t sb, int lane, int m0w, int n0w, float acc[4][4][4])
{
#pragma unroll
    for (int s = 0; s < 2; s++) {
        uint32_t ah[4][4], al[4][4], bh[4][2], bl[4][2];
#pragma unroll
        for (int mi = 0; mi < 4; mi++) {
            int row = m0w + mi * 16 + (lane & 15);
            int j = s * 2 + (lane >> 4);
            uint32_t ad = sb + row * 64 + ((j ^ (row & 3)) << 4);
            LDSM4(ah[mi][0], ah[mi][1], ah[mi][2], ah[mi][3], ad);
            LDSM4(al[mi][0], al[mi][1], al[mi][2], al[mi][3], ad + 8192);
        }
#pragma unroll
        for (int np = 0; np < 2; np++) {
            int q = lane >> 3;
            int row = n0w + np * 16 + ((q >> 1) << 3) + (lane & 7);
            int j = s * 2 + (q & 1);
            uint32_t bd = sb + 16384 + row * 64 + ((j ^ (row & 3)) << 4);
            LDSM4(bh[2 * np][0], bh[2 * np][1], bh[2 * np + 1][0], bh[2 * np + 1][1], bd);
            LDSM4(bl[2 * np][0], bl[2 * np][1], bl[2 * np + 1][0], bl[2 * np + 1][1], bd + 8192);
        }
#pragma unroll
        for (int mi = 0; mi < 4; mi++) {
#pragma unroll
            for (int ni = 0; ni < 4; ni++) {
                MMA_BF16(acc[mi][ni], ah[mi], bh[ni]);
                MMA_BF16(acc[mi][ni], ah[mi], bl[ni]);
                MMA_BF16(acc[mi][ni], al[mi], bh[ni]);
            }
        }
    }
}

__global__ __launch_bounds__(256, 1)
void hmma_gemm(const __nv_bfloat16* __restrict__ Ah, const __nv_bfloat16* __restrict__ Al,
               const __nv_bfloat16* __restrict__ Bh, const __nv_bfloat16* __restrict__ Bl,
               float* __restrict__ C, const float* __restrict__ Res,
               int N, int K,
               long long sA, long long sB, long long sC,
               const int* __restrict__ cnt, int geluMode,
               __nv_bfloat16* __restrict__ Gh, __nv_bfloat16* __restrict__ Gl)
{
    extern __shared__ char sm[];
    const int rowBase = blockIdx.y * 128;
    if (cnt && rowBase >= cnt[blockIdx.z]) return;

    Ah += (long long)blockIdx.z * sA; Al += (long long)blockIdx.z * sA;
    Bh += (long long)blockIdx.z * sB; Bl += (long long)blockIdx.z * sB;

    const int tid = threadIdx.x, wid = tid >> 5, lane = tid & 31;
    const int colBase = blockIdx.x * 128;
    const int m0w = (wid >> 2) * 64, n0w = (wid & 3) * 32;
    uint32_t smb = smem_u32(sm);

    float acc[4][4][4];
#pragma unroll
    for (int mi = 0; mi < 4; mi++)
#pragma unroll
        for (int ni = 0; ni < 4; ni++)
#pragma unroll
            for (int r = 0; r < 4; r++) acc[mi][ni][r] = 0.f;

    const int KC = K >> 5;

    {
        uint32_t sb = smb;
#pragma unroll
        for (int p = 0; p < 2; p++) {
            int idx = tid + p * 256;
            int r = idx >> 2, j = idx & 3;
            uint32_t so = r * 64 + ((j ^ (r & 3)) << 4);
            long long ga = (long long)(rowBase + r) * K + j * 8;
            long long gb = (long long)(colBase + r) * K + j * 8;
            cp16(sb + so,         Ah + ga);
            cp16(sb + 8192 + so,  Al + ga);
            cp16(sb + 16384 + so, Bh + gb);
            cp16(sb + 24576 + so, Bl + gb);
        }
        CP_COMMIT();
    }

    for (int c = 0; c < KC; c++) {
        if (c + 1 < KC) {
            uint32_t sb = smb + ((c + 1) & 1) * STAGE_BYTES;
            long long k0 = (long long)(c + 1) * 32;
#pragma unroll
            for (int p = 0; p < 2; p++) {
                int idx = tid + p * 256;
                int r = idx >> 2, j = idx & 3;
                uint32_t so = r * 64 + ((j ^ (r & 3)) << 4);
                long long ga = (long long)(rowBase + r) * K + k0 + j * 8;
                long long gb = (long long)(colBase + r) * K + k0 + j * 8;
                cp16(sb + so,         Ah + ga);
                cp16(sb + 8192 + so,  Al + ga);
                cp16(sb + 16384 + so, Bh + gb);
                cp16(sb + 24576 + so, Bl + gb);
            }
            CP_COMMIT();
            CP_WAIT(1);
        } else {
            CP_WAIT(0);
        }
        __syncthreads();
        hmma_compute_stage(smb + (c & 1) * STAGE_BYTES, lane, m0w, n0w, acc);
        __syncthreads();
    }

    if (geluMode) {
        const int NH = N >> 1;
        Gh += (long long)blockIdx.z * sC;
        Gl += (long long)blockIdx.z * sC;
#pragma unroll
        for (int mi = 0; mi < 4; mi++) {
#pragma unroll
            for (int ni = 0; ni < 4; ni++) {
                int row = rowBase + m0w + mi * 16 + (lane >> 2);
                int hcol = (colBase + n0w + ni * 8 + (lane & 3) * 2) >> 1;
                float g0 = gelu1(acc[mi][ni][0] * acc[mi][ni][1]);
                float g1 = gelu1(acc[mi][ni][2] * acc[mi][ni][3]);
                __nv_bfloat16 h, l;
                split1(g0, h, l);
                Gh[(long long)row * NH + hcol] = h;
                Gl[(long long)row * NH + hcol] = l;
                split1(g1, h, l);
                Gh[(long long)(row + 8) * NH + hcol] = h;
                Gl[(long long)(row + 8) * NH + hcol] = l;
            }
        }
        return;
    }

    C += (long long)blockIdx.z * sC;
#pragma unroll
    for (int mi = 0; mi < 4; mi++) {
#pragma unroll
        for (int ni = 0; ni < 4; ni++) {
            int row = rowBase + m0w + mi * 16 + (lane >> 2);
            int col = colBase + n0w + ni * 8 + (lane & 3) * 2;
            float2 v0 = make_float2(acc[mi][ni][0], acc[mi][ni][1]);
            float2 v1 = make_float2(acc[mi][ni][2], acc[mi][ni][3]);
            long long o0 = (long long)row * N + col;
            long long o1 = (long long)(row + 8) * N + col;
            if (Res) {
                float2 r0 = *(const float2*)&Res[o0];
                float2 r1 = *(const float2*)&Res[o1];
                v0.x += r0.x; v0.y += r0.y;
                v1.x += r1.x; v1.y += r1.y;
            }
            *(float2*)&C[o0] = v0;
            *(float2*)&C[o1] = v1;
        }
    }
}

// ================= flash attention (HMMA, split-bf16, fp32 softmax) =================
// Block per (q-tile of 128 tokens, hq, b). 8 warps, each owns 16 q-rows.
// K tile [64 keys][64 d], V tile transposed [64 d][64 keys], both hi/lo, double buffered.
// smem: Q 32KB | buf0 32KB {Kh,Kl,Vh,Vl 8KB each} | buf1 32KB
#define AT_SMEM (32768 + 2 * 32768)
#define SW128R(r, c) ((r) * 128 + (((c) ^ ((r) & 7)) << 4))

__global__ __launch_bounds__(256, 1)
void flash_attn(const __nv_bfloat16* __restrict__ Qh, const __nv_bfloat16* __restrict__ Ql,
                const __nv_bfloat16* __restrict__ Kh, const __nv_bfloat16* __restrict__ Kl,
                const __nv_bfloat16* __restrict__ Vh, const __nv_bfloat16* __restrict__ Vl,
                __nv_bfloat16* __restrict__ Oh, __nv_bfloat16* __restrict__ Ol)
{
    extern __shared__ char sm[];
    const int qt = (gridDim.x - 1) - blockIdx.x;   // heavy tiles first
    const int hq = blockIdx.y, b = blockIdx.z;
    const int kvh = hq >> 2;
    const int tid = threadIdx.x, wid = tid >> 5, lane = tid & 31;
    const int q0 = qt * 128;
    uint32_t smb = smem_u32(sm);

    const __nv_bfloat16* qgh = Qh + (((long long)(b * HQ + hq)) * TT + q0) * 64;
    const __nv_bfloat16* qgl = Ql + (((long long)(b * HQ + hq)) * TT + q0) * 64;
    const __nv_bfloat16* kgh = Kh + ((long long)(b * HKV + kvh)) * TT * 64;
    const __nv_bfloat16* kgl = Kl + ((long long)(b * HKV + kvh)) * TT * 64;
    const __nv_bfloat16* vgh = Vh + ((long long)(b * HKV + kvh)) * 64 * TT;
    const __nv_bfloat16* vgl = Vl + ((long long)(b * HKV + kvh)) * 64 * TT;

    // ---- prologue: load Q (hi+lo) and KV tile 0 ----
#pragma unroll
    for (int p = 0; p < 4; p++) {
        int idx = tid + p * 256;
        int r = idx >> 3, c = idx & 7;
        uint32_t so = SW128R(r, c);
        cp16(smb + so,         qgh + r * 64 + c * 8);
        cp16(smb + 16384 + so, qgl + r * 64 + c * 8);
    }
    {
        uint32_t kb = smb + 32768;
#pragma unroll
        for (int p = 0; p < 2; p++) {
            int idx = tid + p * 256;
            int r = idx >> 3, c = idx & 7;
            uint32_t so = SW128R(r, c);
            cp16(kb + so,          kgh + (long long)r * 64 + c * 8);
            cp16(kb + 8192 + so,   kgl + (long long)r * 64 + c * 8);
            cp16(kb + 16384 + so,  vgh + (long long)r * TT + c * 8);
            cp16(kb + 24576 + so,  vgl + (long long)r * TT + c * 8);
        }
        CP_COMMIT();
    }

    uint32_t qfh[4][4], qfl[4][4];
    float o[8][4];
#pragma unroll
    for (int ni = 0; ni < 8; ni++)
#pragma unroll
        for (int r = 0; r < 4; r++) o[ni][r] = 0.f;
    float m0 = -1e30f, m1 = -1e30f, l0 = 0.f, l1 = 0.f;

    const int jmax = 2 * qt + 1;
    for (int j = 0; j <= jmax; j++) {
        if (j < jmax) {
            uint32_t kb = smb + 32768 + ((j + 1) & 1) * 32768;
            long long k0 = (long long)(j + 1) * 64;
#pragma unroll
            for (int p = 0; p < 2; p++) {
                int idx = tid + p * 256;
                int r = idx >> 3, c = idx & 7;
                uint32_t so = SW128R(r, c);
                cp16(kb + so,         kgh + (k0 + r) * 64 + c * 8);
                cp16(kb + 8192 + so,  kgl + (k0 + r) * 64 + c * 8);
                cp16(kb + 16384 + so, vgh + (long long)r * TT + k0 + c * 8);
                cp16(kb + 24576 + so, vgl + (long long)r * TT + k0 + c * 8);
            }
            CP_COMMIT();
            CP_WAIT(1);
        } else {
            CP_WAIT(0);
        }
        __syncthreads();

        if (j == 0) {
#pragma unroll
            for (int ks = 0; ks < 4; ks++) {
                int row = wid * 16 + (lane & 15);
                int ch = ks * 2 + (lane >> 4);
                uint32_t ad = smb + SW128R(row, ch);
                LDSM4(qfh[ks][0], qfh[ks][1], qfh[ks][2], qfh[ks][3], ad);
                LDSM4(qfl[ks][0], qfl[ks][1], qfl[ks][2], qfl[ks][3], ad + 16384);
            }
        }

        uint32_t kb = smb + 32768 + (j & 1) * 32768;
        // ---- S = Q K^T (3-term split) ----
        float sc[8][4];
#pragma unroll
        for (int ni = 0; ni < 8; ni++)
#pragma unroll
            for (int r = 0; r < 4; r++) sc[ni][r] = 0.f;
#pragma unroll
        for (int ks = 0; ks < 4; ks++) {
#pragma unroll
            for (int np = 0; np < 4; np++) {
                int q = lane >> 3;
                int row = np * 16 + ((q >> 1) << 3) + (lane & 7);
                int ch = ks * 2 + (q & 1);
                uint32_t ad = kb + SW128R(row, ch);
                uint32_t kh4[4], kl4[4];
                LDSM4(kh4[0], kh4[1], kh4[2], kh4[3], ad);
                LDSM4(kl4[0], kl4[1], kl4[2], kl4[3], ad + 8192);
                MMA_BF16(sc[2 * np],     qfh[ks], (&kh4[0]));
                MMA_BF16(sc[2 * np],     qfh[ks], (&kl4[0]));
                MMA_BF16(sc[2 * np],     qfl[ks], (&kh4[0]));
                MMA_BF16(sc[2 * np + 1], qfh[ks], (&kh4[2]));
                MMA_BF16(sc[2 * np + 1], qfh[ks], (&kl4[2]));
                MMA_BF16(sc[2 * np + 1], qfl[ks], (&kh4[2]));
            }
        }
        // scale + causal mask
        int r0 = q0 + wid * 16 + (lane >> 2);
        int r1 = r0 + 8;
#pragma unroll
        for (int ni = 0; ni < 8; ni++) {
#pragma unroll
            for (int r = 0; r < 4; r++) sc[ni][r] *= 0.125f;
        }
        if (j >= 2 * qt) {
#pragma unroll
            for (int ni = 0; ni < 8; ni++) {
                int kc = j * 64 + ni * 8 + (lane & 3) * 2;
                if (kc     > r0) sc[ni][0] = -1e30f;
                if (kc + 1 > r0) sc[ni][1] = -1e30f;
                if (kc     > r1) sc[ni][2] = -1e30f;
                if (kc + 1 > r1) sc[ni][3] = -1e30f;
            }
        }
        // ---- online softmax (fp32) ----
        float tm0 = -1e30f, tm1 = -1e30f;
#pragma unroll
        for (int ni = 0; ni < 8; ni++) {
            tm0 = fmaxf(tm0, fmaxf(sc[ni][0], sc[ni][1]));
            tm1 = fmaxf(tm1, fmaxf(sc[ni][2], sc[ni][3]));
        }
        tm0 = fmaxf(tm0, __shfl_xor_sync(0xffffffffu, tm0, 1));
        tm0 = fmaxf(tm0, __shfl_xor_sync(0xffffffffu, tm0, 2));
        tm1 = fmaxf(tm1, __shfl_xor_sync(0xffffffffu, tm1, 1));
        tm1 = fmaxf(tm1, __shfl_xor_sync(0xffffffffu, tm1, 2));
        float mn0 = fmaxf(m0, tm0), mn1 = fmaxf(m1, tm1);
        float al0 = __expf(m0 - mn0), al1 = __expf(m1 - mn1);
        m0 = mn0; m1 = mn1;
        l0 *= al0; l1 *= al1;
#pragma unroll
        for (int ni = 0; ni < 8; ni++) {
            o[ni][0] *= al0; o[ni][1] *= al0;
            o[ni][2] *= al1; o[ni][3] *= al1;
        }
        float rs0 = 0.f, rs1 = 0.f;
#pragma unroll
        for (int ni = 0; ni < 8; ni++) {
            float p0 = __expf(sc[ni][0] - m0); sc[ni][0] = p0;
            float p1 = __expf(sc[ni][1] - m0); sc[ni][1] = p1;
            float p2 = __expf(sc[ni][2] - m1); sc[ni][2] = p2;
            float p3 = __expf(sc[ni][3] - m1); sc[ni][3] = p3;
            rs0 += p0 + p1; rs1 += p2 + p3;
        }
        rs0 += __shfl_xor_sync(0xffffffffu, rs0, 1);
        rs0 += __shfl_xor_sync(0xffffffffu, rs0, 2);
        rs1 += __shfl_xor_sync(0xffffffffu, rs1, 1);
        rs1 += __shfl_xor_sync(0xffffffffu, rs1, 2);
        l0 += rs0; l1 += rs1;
        // ---- P fragments (hi/lo split) ----
        uint32_t ph[4][4], pl[4][4];
#pragma unroll
        for (int ks = 0; ks < 4; ks++) {
            split2pack(sc[2 * ks][0],     sc[2 * ks][1],     ph[ks][0], pl[ks][0]);
            split2pack(sc[2 * ks][2],     sc[2 * ks][3],     ph[ks][1], pl[ks][1]);
            split2pack(sc[2 * ks + 1][0], sc[2 * ks + 1][1], ph[ks][2], pl[ks][2]);
            split2pack(sc[2 * ks + 1][2], sc[2 * ks + 1][3], ph[ks][3], pl[ks][3]);
        }
        // ---- O += P V (3-term split) ----
#pragma unroll
        for (int ks = 0; ks < 4; ks++) {
#pragma unroll
            for (int np = 0; np < 4; np++) {
                int q = lane >> 3;
                int row = np * 16 + ((q >> 1) << 3) + (lane & 7);
                int ch = ks * 2 + (q & 1);
                uint32_t ad = kb + 16384 + SW128R(row, ch);
                uint32_t vh4[4], vl4[4];
                LDSM4(vh4[0], vh4[1], vh4[2], vh4[3], ad);
                LDSM4(vl4[0], vl4[1], vl4[2], vl4[3], ad + 8192);
                MMA_BF16(o[2 * np],     ph[ks], (&vh4[0]));
                MMA_BF16(o[2 * np],     ph[ks], (&vl4[0]));
                MMA_BF16(o[2 * np],     pl[ks], (&vh4[0]));
                MMA_BF16(o[2 * np + 1], ph[ks], (&vh4[2]));
                MMA_BF16(o[2 * np + 1], ph[ks], (&vl4[2]));
                MMA_BF16(o[2 * np + 1], pl[ks], (&vh4[2]));
            }
        }
        __syncthreads();
    }

    // ---- epilogue ----
    float inv0 = 1.0f / l0, inv1 = 1.0f / l1;
    int r0 = q0 + wid * 16 + (lane >> 2);
    int r1 = r0 + 8;
#pragma unroll
    for (int ni = 0; ni < 8; ni++) {
        int col = ni * 8 + (lane & 3) * 2;
        long long i0 = (((long long)(b * TT + r0)) * HQ + hq) * 64 + col;
        long long i1 = (((long long)(b * TT + r1)) * HQ + hq) * 64 + col;
        uint32_t h, l;
        split2pack(o[ni][0] * inv0, o[ni][1] * inv0, h, l);
        *(uint32_t*)&Oh[i0] = h; *(uint32_t*)&Ol[i0] = l;
        split2pack(o[ni][2] * inv1, o[ni][3] * inv1, h, l);
        *(uint32_t*)&Oh[i1] = h; *(uint32_t*)&Ol[i1] = l;
    }
}

// ================= prepack kernels =================
__global__ void tsplit_kernel(const float* __restrict__ W,
                              __nv_bfloat16* __restrict__ Th, __nv_bfloat16* __restrict__ Tl,
                              int K, int N, long long sW, long long sT,
                              int rowMul, int rowAdd) {
    __shared__ float tile[32][33];
    W  += (long long)blockIdx.z * sW;
    Th += (long long)blockIdx.z * sT;
    Tl += (long long)blockIdx.z * sT;
    int n0 = blockIdx.x * 32, k0 = blockIdx.y * 32;
    int tx = threadIdx.x, ty = threadIdx.y;
    for (int i = ty; i < 32; i += 8)
        tile[i][tx] = W[(long long)(k0 + i) * N + n0 + tx];
    __syncthreads();
    for (int i = ty; i < 32; i += 8) {
        float v = tile[tx][i];
        __nv_bfloat16 h, l; split1(v, h, l);
        long long o = ((long long)(n0 + i) * rowMul + rowAdd) * K + k0 + tx;
        Th[o] = h; Tl[o] = l;
    }
}

__global__ void split_kernel(const float* __restrict__ X,
                             __nv_bfloat16* __restrict__ H, __nv_bfloat16* __restrict__ L,
                             long long n) {
    long long i = (long long)blockIdx.x * blockDim.x + threadIdx.x;
    long long stride = (long long)gridDim.x * blockDim.x;
    for (; i < n; i += stride) {
        __nv_bfloat16 h, l; split1(X[i], h, l);
        H[i] = h; L[i] = l;
    }
}

// pack q,k with fused rope -> split-bf16, head-major layouts
__global__ void qk_pack(const float* __restrict__ qkv,
                        __nv_bfloat16* __restrict__ Qh, __nv_bfloat16* __restrict__ Ql,
                        __nv_bfloat16* __restrict__ Kh, __nv_bfloat16* __restrict__ Kl) {
    long long i = (long long)blockIdx.x * blockDim.x + threadIdx.x;
    if (i >= (long long)NTOK * 20 * 32) return;
    int half = (int)(i & 31);
    long long rest = i >> 5;
    int head = (int)(rest % 20);
    long long tok = rest / 20;
    int t = (int)(tok & (TT - 1));
    int b = (int)(tok >> 10);
    int colOff = head < 16 ? head * 64 : 1024 + (head - 16) * 64;
    const float* src = qkv + tok * QKVN + colOff;
    float x1 = src[half], x2 = src[half + 32];
    float theta = __powf(10000.0f, -(float)(2 * half) / 64.0f);
    float ang = (float)t * theta;
    float s = sinf(ang), c = cosf(ang);
    float y1 = x1 * c - x2 * s;
    float y2 = x2 * c + x1 * s;
    __nv_bfloat16 h, l;
    if (head < 16) {
        long long d = (((long long)(b * HQ + head)) * TT + t) * 64;
        split1(y1, h, l); Qh[d + half] = h;      Ql[d + half] = l;
        split1(y2, h, l); Qh[d + half + 32] = h; Ql[d + half + 32] = l;
    } else {
        long long d = (((long long)(b * HKV + head - 16)) * TT + t) * 64;
        split1(y1, h, l); Kh[d + half] = h;      Kl[d + half] = l;
        split1(y2, h, l); Kh[d + half + 32] = h; Kl[d + half + 32] = l;
    }
}

// pack v transposed: [tok][d] -> [d][tok], split-bf16
__global__ void v_pack(const float* __restrict__ qkv,
                       __nv_bfloat16* __restrict__ Vh, __nv_bfloat16* __restrict__ Vl) {
    __shared__ float tile[32][33];
    int z = blockIdx.z;                 // b*HKV + kvh
    int b = z >> 2, kvh = z & 3;
    int t0 = blockIdx.x * 32, d0 = blockIdx.y * 32;
    int tx = threadIdx.x, ty = threadIdx.y;
    for (int i = ty; i < 32; i += 8)
        tile[i][tx] = qkv[((long long)(b * TT + t0 + i)) * QKVN + 1280 + kvh * 64 + d0 + tx];
    __syncthreads();
    for (int i = ty; i < 32; i += 8) {
        float v = tile[tx][i];          // [tok t0+tx][d d0+i]
        __nv_bfloat16 h, l; split1(v, h, l);
        long long o = ((long long)z * 64 + d0 + i) * TT + t0 + tx;
        Vh[o] = h; Vl[o] = l;
    }
}

// ================= rmsnorm =================
__global__ void rmsnorm_kernel(const float* __restrict__ x, const float* __restrict__ scale,
                               float* __restrict__ out) {
    int n = blockIdx.x, tid = threadIdx.x;
    __shared__ float red[256];
    const float* xr = x + (long long)n * DD;
    float ss = 0.f;
    for (int d = tid; d < DD; d += 256) { float v = xr[d]; ss += v * v; }
    red[tid] = ss; __syncthreads();
    for (int s = 128; s > 0; s >>= 1) { if (tid < s) red[tid] += red[tid + s]; __syncthreads(); }
    float inv = rsqrtf(red[0] / (float)DD + EPS);
    float* o = out + (long long)n * DD;
    for (int d = tid; d < DD; d += 256) o[d] = xr[d] * inv * scale[d];
}

__global__ void rmsnorm_split_kernel(const float* __restrict__ x, const float* __restrict__ scale,
                                     __nv_bfloat16* __restrict__ oh, __nv_bfloat16* __restrict__ ol) {
    int n = blockIdx.x, tid = threadIdx.x;
    __shared__ float red[256];
    const float* xr = x + (long long)n * DD;
    float ss = 0.f;
    for (int d = tid; d < DD; d += 256) { float v = xr[d]; ss += v * v; }
    red[tid] = ss; __syncthreads();
    for (int s = 128; s > 0; s >>= 1) { if (tid < s) red[tid] += red[tid + s]; __syncthreads(); }
    float inv = rsqrtf(red[0] / (float)DD + EPS);
    for (int d = tid; d < DD; d += 256) {
        float o = xr[d] * inv * scale[d];
        __nv_bfloat16 h, l; split1(o, h, l);
        oh[(long long)n * DD + d] = h;
        ol[(long long)n * DD + d] = l;
    }
}

// ================= router / capacity / dispatch / combine =================
__global__ void router_kernel(const float* __restrict__ h2, const float* __restrict__ rw,
                              const float* __restrict__ rb,
                              float* __restrict__ gate, int* __restrict__ expert) {
    int n = blockIdx.x, tid = threadIdx.x;
    __shared__ float part[128][8];
    float acc[8];
#pragma unroll
    for (int e = 0; e < 8; e++) acc[e] = 0.f;
    const float* xr = h2 + (long long)n * DD;
    for (int d = tid; d < DD; d += 128) {
        float xv = xr[d];
#pragma unroll
        for (int e = 0; e < 8; e++) acc[e] += xv * rw[d * 8 + e];
    }
#pragma unroll
    for (int e = 0; e < 8; e++) part[tid][e] = acc[e];
    __syncthreads();
    if (tid < 8) {
        float s = rb[tid];
        for (int i = 0; i < 128; i++) s += part[i][tid];
        part[0][tid] = s;
    }
    __syncthreads();
    if (tid == 0) {
        float lg[8];
#pragma unroll
        for (int e = 0; e < 8; e++) lg[e] = part[0][e];
        int i0 = 0;
        for (int e = 1; e < 8; e++) if (lg[e] > lg[i0]) i0 = e;
        int i1 = -1;
        for (int e = 0; e < 8; e++) {
            if (e == i0) continue;
            if (i1 < 0 || lg[e] > lg[i1]) i1 = e;
        }
        float a = lg[i0], bq = lg[i1];
        float ea = 1.0f, eb = expf(bq - a);
        float s = ea + eb;
        gate[n * 2] = ea / s; gate[n * 2 + 1] = eb / s;
        expert[n * 2] = i0;   expert[n * 2 + 1] = i1;
    }
}

__global__ void capacity_kernel(const int* __restrict__ expert,
                                int* __restrict__ slot, int* __restrict__ keep,
                                int* __restrict__ cnt) {
    int w = threadIdx.x >> 5;
    int lane = threadIdx.x & 31;
    if (w >= EE) return;
    int c0 = 0, c1 = 0;
    unsigned le = 0xffffffffu >> (31 - lane);
    for (int base = 0; base < NTOK; base += 32) {
        int n = base + lane;
        int e0 = expert[n * 2], e1 = expert[n * 2 + 1];
        unsigned m0 = __ballot_sync(0xffffffffu, e0 == w);
        unsigned m1 = __ballot_sync(0xffffffffu, e1 == w);
        int inc0 = __popc(m0 & le);
        int inc1 = __popc(m1 & le);
        if (e0 == w) {
            int p0 = c0 + inc0;
            keep[n * 2] = (p0 < CAP) ? 1 : 0;
            slot[n * 2] = p0;
        }
        if (e1 == w) {
            int p1 = c0 + inc0 + c1 + inc1;
            keep[n * 2 + 1] = (p1 < CAP) ? 1 : 0;
            slot[n * 2 + 1] = p1;
        }
        c0 += __popc(m0); c1 += __popc(m1);
    }
    if (lane == 0) {
        int tot = c0 + c1 + 1;
        cnt[w] = tot < CAP ? tot : CAP;
    }
}

__global__ void dispatch_kernel(const float* __restrict__ h2, const int* __restrict__ expert,
                                const int* __restrict__ slot, const int* __restrict__ keep,
                                float* __restrict__ grouped) {
    int idx = blockIdx.x;
    if (!keep[idx]) return;
    int n = idx >> 1;
    int e = expert[idx], p = slot[idx];
    float* dst = grouped + ((long long)e * CAP + p) * DD;
    const float* src = h2 + (long long)n * DD;
    for (int d = threadIdx.x; d < DD; d += blockDim.x) atomicAdd(&dst[d], src[d]);
}

__global__ void combine_kernel(const float* __restrict__ x1, const float* __restrict__ h2,
                               const float* __restrict__ eout, const float* __restrict__ gate,
                               const int* __restrict__ expert, const int* __restrict__ slot,
                               const int* __restrict__ keep, float* __restrict__ out) {
    int n = blockIdx.x, tid = threadIdx.x;
    float g0 = gate[n * 2], g1 = gate[n * 2 + 1];
    const float* s0 = keep[n * 2]
        ? eout + ((long long)expert[n * 2] * CAP + slot[n * 2]) * DD
        : h2 + (long long)n * DD;
    const float* s1 = keep[n * 2 + 1]
        ? eout + ((long long)expert[n * 2 + 1] * CAP + slot[n * 2 + 1]) * DD
        : h2 + (long long)n * DD;
    const float* xr = x1 + (long long)n * DD;
    float* o = out + (long long)n * DD;
    for (int d = tid; d < DD; d += 256)
        o[d] = xr[d] + g0 * s0[d] + g1 * s1[d];
}

// ================= host launch =================
template <typename T>
static T* sym_addr(const void* sym) {
    void* p = nullptr;
    cudaGetSymbolAddress(&p, sym);
    return (T*)p;
}

#define HM_SMEM (2 * STAGE_BYTES)

extern "C" void kernel_launch(void* const* d_in, const int* in_sizes, int n_in,
                              void* d_out, int out_size) {
    const float* x   = (const float*)d_in[0];
    const float* wq  = (const float*)d_in[1];
    const float* wk  = (const float*)d_in[2];
    const float* wv  = (const float*)d_in[3];
    const float* wo  = (const float*)d_in[4];
    const float* rw  = (const float*)d_in[5];
    const float* rb  = (const float*)d_in[6];
    const float* w1  = (const float*)d_in[7];
    const float* w2  = (const float*)d_in[8];
    const float* w3  = (const float*)d_in[9];
    const float* n1s = (const float*)d_in[10];
    const float* n2s = (const float*)d_in[11];
    float* out = (float*)d_out;

    cudaFuncSetAttribute(hmma_gemm, cudaFuncAttributeMaxDynamicSharedMemorySize, HM_SMEM);
    cudaFuncSetAttribute(flash_attn, cudaFuncAttributeMaxDynamicSharedMemorySize, AT_SMEM);

    float* pqkv  = sym_addr<float>(g_qkv);
    float* px1   = sym_addr<float>(g_x1);
    float* ph2   = sym_addr<float>(g_h2);
    float* pgate = sym_addr<float>(g_gate);
    int*   pexp  = sym_addr<int>(g_expert);
    int*   pslot = sym_addr<int>(g_slot);
    int*   pkeep = sym_addr<int>(g_keep);
    int*   pcnt  = sym_addr<int>(g_cnt);
    float* pgrp  = sym_addr<float>(g_grouped);
    float* peout = sym_addr<float>(g_eout);

    __nv_bfloat16* phh  = sym_addr<__nv_bfloat16>(g_hh);
    __nv_bfloat16* phl  = sym_addr<__nv_bfloat16>(g_hl);
    __nv_bfloat16* path = sym_addr<__nv_bfloat16>(g_ath);
    __nv_bfloat16* patl = sym_addr<__nv_bfloat16>(g_atl);
    __nv_bfloat16* pgh  = sym_addr<__nv_bfloat16>(g_grph);
    __nv_bfloat16* pgl  = sym_addr<__nv_bfloat16>(g_grpl);
    __nv_bfloat16* pt1h = sym_addr<__nv_bfloat16>(g_t1h);
    __nv_bfloat16* pt1l = sym_addr<__nv_bfloat16>(g_t1l);

    __nv_bfloat16* pqph = sym_addr<__nv_bfloat16>(g_qph);
    __nv_bfloat16* pqpl = sym_addr<__nv_bfloat16>(g_qpl);
    __nv_bfloat16* pkph = sym_addr<__nv_bfloat16>(g_kph);
    __nv_bfloat16* pkpl = sym_addr<__nv_bfloat16>(g_kpl);
    __nv_bfloat16* pvph = sym_addr<__nv_bfloat16>(g_vph);
    __nv_bfloat16* pvpl = sym_addr<__nv_bfloat16>(g_vpl);

    __nv_bfloat16* pwqkvh = sym_addr<__nv_bfloat16>(g_wqkvh);
    __nv_bfloat16* pwqkvl = sym_addr<__nv_bfloat16>(g_wqkvl);
    __nv_bfloat16* pwoh = sym_addr<__nv_bfloat16>(g_woh);
    __nv_bfloat16* pwol = sym_addr<__nv_bfloat16>(g_wol);
    __nv_bfloat16* pw12h = sym_addr<__nv_bfloat16>(g_w12h);
    __nv_bfloat16* pw12l = sym_addr<__nv_bfloat16>(g_w12l);
    __nv_bfloat16* pw3h = sym_addr<__nv_bfloat16>(g_w3h);
    __nv_bfloat16* pw3l = sym_addr<__nv_bfloat16>(g_w3l);

    dim3 tb(32, 8);
    // ---- attention-path prepack ----
    rmsnorm_split_kernel<<<NTOK, 256>>>(x, n1s, phh, phl);
    tsplit_kernel<<<dim3(DD / 32, DD / 32, 1), tb>>>(wq, pwqkvh, pwqkvl, DD, DD, 0, 0, 1, 0);
    tsplit_kernel<<<dim3(256 / 32, DD / 32, 1), tb>>>(wk, pwqkvh + 1024 * DD, pwqkvl + 1024 * DD, DD, 256, 0, 0, 1, 0);
    tsplit_kernel<<<dim3(256 / 32, DD / 32, 1), tb>>>(wv, pwqkvh + 1280 * DD, pwqkvl + 1280 * DD, DD, 256, 0, 0, 1, 0);
    tsplit_kernel<<<dim3(DD / 32, DD / 32, 1), tb>>>(wo, pwoh, pwol, DD, DD, 0, 0, 1, 0);

    // fused QKV GEMM, N=1536
    hmma_gemm<<<dim3(QKVN / 128, NTOK / 128, 1), 256, HM_SMEM>>>(
        phh, phl, pwqkvh, pwqkvl, pqkv, nullptr, QKVN, DD, 0, 0, 0,
        nullptr, 0, nullptr, nullptr);

    // pack q/k (rope fused) + v (transposed), then tensor-core flash attention
    {
        long long tot = (long long)NTOK * 20 * 32;
        qk_pack<<<(int)((tot + 255) / 256), 256>>>(pqkv, pqph, pqpl, pkph, pkpl);
    }
    v_pack<<<dim3(TT / 32, 2, BB * HKV), tb>>>(pqkv, pvph, pvpl);
    flash_attn<<<dim3(TT / 128, HQ, BB), 256, AT_SMEM>>>(
        pqph, pqpl, pkph, pkpl, pvph, pvpl, path, patl);

    hmma_gemm<<<dim3(8, 16, 1), 256, HM_SMEM>>>(path, patl, pwoh, pwol, px1, x, 1024, HQ * VD, 0, 0, 0,
        nullptr, 0, nullptr, nullptr);

    // ---- MoE weight prepack (w1/w2 row-interleaved for fused gelu) ----
    tsplit_kernel<<<dim3(HID / 32, DD / 32, EE), tb>>>(w1, pw12h, pw12l, DD, HID,
        (long long)DD * HID, (long long)(2 * HID) * DD, 2, 0);
    tsplit_kernel<<<dim3(HID / 32, DD / 32, EE), tb>>>(w2, pw12h, pw12l, DD, HID,
        (long long)DD * HID, (long long)(2 * HID) * DD, 2, 1);
    tsplit_kernel<<<dim3(DD / 32, HID / 32, EE), tb>>>(w3, pw3h, pw3l, HID, DD,
        (long long)HID * DD, (long long)HID * DD, 1, 0);

    rmsnorm_kernel<<<NTOK, 256>>>(px1, n2s, ph2);
    router_kernel<<<NTOK, 128>>>(ph2, rw, rb, pgate, pexp);
    capacity_kernel<<<1, 256>>>(pexp, pslot, pkeep, pcnt);
    cudaMemsetAsync(pgrp, 0, (size_t)EE * CAP * DD * sizeof(float));
    dispatch_kernel<<<NTOK * TOPK, 256>>>(ph2, pexp, pslot, pkeep, pgrp);
    split_kernel<<<2048, 256>>>(pgrp, pgh, pgl, (long long)EE * CAP * DD);

    // fused w1|w2 GEMM with gelu epilogue -> split-bf16 t1 (zero-row tiles skipped)
    hmma_gemm<<<dim3((2 * HID) / 128, CAP / 128, EE), 256, HM_SMEM>>>(
        pgh, pgl, pw12h, pw12l, nullptr, nullptr,
        2 * HID, DD, (long long)CAP * DD, (long long)(2 * HID) * DD, (long long)CAP * HID,
        pcnt, 1, pt1h, pt1l);
    // w3 GEMM (zero-row tiles skipped)
    hmma_gemm<<<dim3(DD / 128, CAP / 128, EE), 256, HM_SMEM>>>(
        pt1h, pt1l, pw3h, pw3l, peout, nullptr,
        DD, HID, (long long)CAP * HID, (long long)HID * DD, (long long)CAP * DD,
        pcnt, 0, nullptr, nullptr);
    combine_kernel<<<NTOK, 256>>>(px1, ph2, peout, pgate, pexp, pslot, pkeep, out);
}